// round 13
// baseline (speedup 1.0000x reference)
#include <cuda_runtime.h>
#include <cstdint>

// ---------------- problem constants ----------------
#define NMAX 10000
#define EMAX 640000
#define DDIM 128
#define EDIM 64
#define HDS  8
#define OUTD 128

// ---------------- device scratch ----------------
__device__ __align__(16) float g_q[NMAX * DDIM];
__device__ __align__(16) float g_k[NMAX * DDIM];
__device__ __align__(16) float g_u[NMAX * OUTD];
__device__ __align__(16) float g_v[NMAX * OUTD];
__device__ __align__(16) float g_P[NMAX * HDS * OUTD];
__device__ __align__(16) float g_a[EMAX * HDS];     // exp(logit), by ORIGINAL edge id
__device__ __align__(16) float g_s[NMAX * HDS];     // segment sums -> 0.25/(s+eps)
__device__ __align__(16) float g_WcT[OUTD * OUTD];
// duplicated Wre, split into two conflict-free planes
__device__ __align__(16) float4 g_wa[EDIM * 32];
__device__ __align__(16) float4 g_wb[EDIM * 32];
__device__ int g_is64;
__device__ int g_nj[EMAX];
__device__ int g_ni[EMAX];
__device__ int g_cnt[NMAX];
__device__ int g_start[NMAX + 1];
__device__ int g_off[NMAX];
__device__ int g_elist[EMAX];

// ---------------- helpers ----------------
__device__ __forceinline__ unsigned long long pack2(float x) {
    unsigned long long r; unsigned u = __float_as_uint(x);
    asm("mov.b64 %0, {%1, %1};" : "=l"(r) : "r"(u));
    return r;
}
__device__ __forceinline__ void fma2(unsigned long long& d, unsigned long long a, unsigned long long b) {
    asm("fma.rn.f32x2 %0, %1, %2, %0;" : "+l"(d) : "l"(a), "l"(b));
}
__device__ __forceinline__ void unpack2(unsigned long long v, float& x, float& y) {
    unsigned a, b;
    asm("mov.b64 {%0, %1}, %2;" : "=r"(a), "=r"(b) : "l"(v));
    x = __uint_as_float(a); y = __uint_as_float(b);
}
__device__ __forceinline__ float siluf(float x) { return __fdividef(x, 1.0f + __expf(-x)); }
__device__ __forceinline__ int load_idx(const void* eidx, int is64, long long pos) {
    return is64 ? (int)((const long long*)eidx)[pos] : ((const int*)eidx)[pos];
}

// ---------------- 1) init (+ index-width detection in block 0) ----------------
__global__ void init_kernel(const float* __restrict__ Wc, const unsigned* __restrict__ ew,
                            int NH, int Nn) {
    if (blockIdx.x == 0) {
        __shared__ int any;
        if (threadIdx.x == 0) any = 0;
        __syncthreads();
        #pragma unroll
        for (int k = 0; k < 4; k++) {
            int i = threadIdx.x + k * 256;
            if (ew[i * 2 + 1] != 0u) any = 1;
        }
        __syncthreads();
        if (threadIdx.x == 0) g_is64 = (any == 0) ? 1 : 0;
    }
    int i = blockIdx.x * blockDim.x + threadIdx.x;
    if (i < NH) g_s[i] = 0.0f;
    if (i < Nn) g_cnt[i] = 0;
    if (i < OUTD * OUTD) {
        int o = i >> 7, d = i & 127;
        g_WcT[d * OUTD + o] = Wc[i];
    }
}

// ---------------- 2) convert indices + histogram, fused with Wre plane prep ----------------
__global__ void convert_hist_wdup_kernel(const void* __restrict__ eidx,
                                         const float* __restrict__ Wre,
                                         int E, int eBlocks) {
    if (blockIdx.x >= eBlocks) {
        int idx = (blockIdx.x - eBlocks) * blockDim.x + threadIdx.x;  // 0..4095
        if (idx < EDIM * 32 * 2) {
            int which = idx >> 11;
            int rem = idx & 2047;
            int j = rem >> 5, l = rem & 31;
            int d0 = l * 4 + which * 2;
            float v0 = Wre[d0 * EDIM + j];
            float v1 = Wre[(d0 + 1) * EDIM + j];
            float4 out = make_float4(v0, v0, v1, v1);
            if (which == 0) g_wa[j * 32 + l] = out;
            else            g_wb[j * 32 + l] = out;
        }
        return;
    }
    int e = blockIdx.x * blockDim.x + threadIdx.x;
    if (e >= E) return;
    int is64 = g_is64;
    int nj = load_idx(eidx, is64, e);
    int ni = load_idx(eidx, is64, (long long)E + e);
    g_nj[e] = nj;
    g_ni[e] = ni;
    atomicAdd(&g_cnt[nj], 1);
}

// ---------------- 3) node GEMMs (32-row tile, 4x4 reg block) ----------------
#define PADW 132
#define PADA 36
__global__ __launch_bounds__(256)
void gemm3_kernel(const float* __restrict__ A,
                  const float* __restrict__ W0, const float* __restrict__ B0,
                  const float* __restrict__ W1p, const float* __restrict__ B1,
                  const float* __restrict__ W2p, const float* __restrict__ B2,
                  float* __restrict__ C0, float* __restrict__ C1, float* __restrict__ C2,
                  int M) {
    const float* W = (blockIdx.y == 0) ? W0 : (blockIdx.y == 1) ? W1p : W2p;
    const float* bias = (blockIdx.y == 0) ? B0 : (blockIdx.y == 1) ? B1 : B2;
    float* C = (blockIdx.y == 0) ? C0 : (blockIdx.y == 1) ? C1 : C2;
    int act = (blockIdx.y == 2);

    __shared__ float wsm[64 * PADW];
    __shared__ float asmv[64 * PADA];
    __shared__ float bsm[128];

    int tid = threadIdx.x;
    int row0 = blockIdx.x * 32;
    int nIdx = tid & 31, mIdx = tid >> 5;
    int n0 = nIdx * 4, m0 = mIdx * 4;
    if (tid < 128) bsm[tid] = bias[tid];

    unsigned long long acc2[4][2] = {};
    for (int kt = 0; kt < DDIM; kt += 64) {
        for (int idx = tid; idx < 128 * 64; idx += 256) {
            int o = idx >> 6, jj = idx & 63;
            wsm[jj * PADW + o] = W[o * DDIM + kt + jj];
        }
        for (int idx = tid; idx < 32 * 64; idx += 256) {
            int m = idx >> 6, jj = idx & 63;
            int r = row0 + m;
            asmv[jj * PADA + m] = (r < M) ? A[r * DDIM + kt + jj] : 0.0f;
        }
        __syncthreads();
        #pragma unroll 16
        for (int j = 0; j < 64; j++) {
            ulonglong2 wv = *(const ulonglong2*)&wsm[j * PADW + n0];
            float4 av = *(const float4*)&asmv[j * PADA + m0];
            unsigned long long a0 = pack2(av.x), a1 = pack2(av.y),
                               a2 = pack2(av.z), a3 = pack2(av.w);
            fma2(acc2[0][0], a0, wv.x); fma2(acc2[0][1], a0, wv.y);
            fma2(acc2[1][0], a1, wv.x); fma2(acc2[1][1], a1, wv.y);
            fma2(acc2[2][0], a2, wv.x); fma2(acc2[2][1], a2, wv.y);
            fma2(acc2[3][0], a3, wv.x); fma2(acc2[3][1], a3, wv.y);
        }
        __syncthreads();
    }
    #pragma unroll
    for (int mi = 0; mi < 4; mi++) {
        int r = row0 + m0 + mi;
        if (r < M) {
            float v0, v1, v2, v3;
            unpack2(acc2[mi][0], v0, v1);
            unpack2(acc2[mi][1], v2, v3);
            v0 += bsm[n0 + 0]; v1 += bsm[n0 + 1]; v2 += bsm[n0 + 2]; v3 += bsm[n0 + 3];
            if (act) { v0 = siluf(v0); v1 = siluf(v1); v2 = siluf(v2); v3 = siluf(v3); }
            *(float4*)&C[r * 128 + n0] = make_float4(v0, v1, v2, v3);
        }
    }
}

__global__ __launch_bounds__(256)
void gemm_kernel(const float* __restrict__ A, const float* __restrict__ W,
                 const float* __restrict__ bias, float* __restrict__ C, int M) {
    __shared__ float wsm[64 * PADW];
    __shared__ float asmv[64 * PADA];
    __shared__ float bsm[128];

    int tid = threadIdx.x;
    int row0 = blockIdx.x * 32;
    int nIdx = tid & 31, mIdx = tid >> 5;
    int n0 = nIdx * 4, m0 = mIdx * 4;
    if (tid < 128) bsm[tid] = bias[tid];

    unsigned long long acc2[4][2] = {};
    for (int kt = 0; kt < OUTD; kt += 64) {
        for (int idx = tid; idx < 128 * 64; idx += 256) {
            int o = idx >> 6, jj = idx & 63;
            wsm[jj * PADW + o] = W[o * OUTD + kt + jj];
        }
        for (int idx = tid; idx < 32 * 64; idx += 256) {
            int m = idx >> 6, jj = idx & 63;
            int r = row0 + m;
            asmv[jj * PADA + m] = (r < M) ? A[r * OUTD + kt + jj] : 0.0f;
        }
        __syncthreads();
        #pragma unroll 16
        for (int j = 0; j < 64; j++) {
            ulonglong2 wv = *(const ulonglong2*)&wsm[j * PADW + n0];
            float4 av = *(const float4*)&asmv[j * PADA + m0];
            unsigned long long a0 = pack2(av.x), a1 = pack2(av.y),
                               a2 = pack2(av.z), a3 = pack2(av.w);
            fma2(acc2[0][0], a0, wv.x); fma2(acc2[0][1], a0, wv.y);
            fma2(acc2[1][0], a1, wv.x); fma2(acc2[1][1], a1, wv.y);
            fma2(acc2[2][0], a2, wv.x); fma2(acc2[2][1], a2, wv.y);
            fma2(acc2[3][0], a3, wv.x); fma2(acc2[3][1], a3, wv.y);
        }
        __syncthreads();
    }
    #pragma unroll
    for (int mi = 0; mi < 4; mi++) {
        int r = row0 + m0 + mi;
        if (r < M) {
            float v0, v1, v2, v3;
            unpack2(acc2[mi][0], v0, v1);
            unpack2(acc2[mi][1], v2, v3);
            v0 += bsm[n0 + 0]; v1 += bsm[n0 + 1]; v2 += bsm[n0 + 2]; v3 += bsm[n0 + 3];
            *(float4*)&C[r * 128 + n0] = make_float4(v0, v1, v2, v3);
        }
    }
}

// ---------------- 4) sort: scan + scatter ----------------
__global__ __launch_bounds__(1024)
void scan_kernel(int Nn) {
    __shared__ int part[1024];
    int t = threadIdx.x;
    int chunk = (Nn + 1023) >> 10;
    int base = t * chunk;
    int local[16];
    int sum = 0;
    for (int i = 0; i < chunk; i++) {
        int idx = base + i;
        int c = (idx < Nn) ? g_cnt[idx] : 0;
        local[i] = sum; sum += c;
    }
    part[t] = sum;
    __syncthreads();
    for (int off = 1; off < 1024; off <<= 1) {
        int v = (t >= off) ? part[t - off] : 0;
        __syncthreads();
        part[t] += v;
        __syncthreads();
    }
    int pre = (t > 0) ? part[t - 1] : 0;
    for (int i = 0; i < chunk; i++) {
        int idx = base + i;
        if (idx < Nn) { int s0 = pre + local[i]; g_start[idx] = s0; g_off[idx] = s0; }
    }
    if (t == 0) g_start[Nn] = part[1023];
}

__global__ void scatter_kernel(int E) {
    int e = blockIdx.x * blockDim.x + threadIdx.x;
    if (e >= E) return;
    int nj = g_nj[e];
    int pos = atomicAdd(&g_off[nj], 1);
    g_elist[pos] = e;
}

// ---------------- 5) edge logits: 64 edges/block, 8/warp, 3 CTAs/SM ----------------
#define ELB 64
#define KC 16
// per-buffer floats: wa[2048], wb[2048], ts[16*68=1088] -> stride 5184
#define BUF_STRIDE 5184
#define OFF_TS 4096
#define OFF_BRE 10368
#define EL_SMEM ((10368 + 128) * 4)   // 41984 bytes

__global__ __launch_bounds__(256, 3)
void edge_logits_kernel(const float* __restrict__ T, const float* __restrict__ bre, int E) {
    extern __shared__ float sm[];
    int tid = threadIdx.x;
    int warp = tid >> 5, lane = tid & 31;
    int eBase = blockIdx.x * ELB;
    if (tid < 128) sm[OFF_BRE + tid] = bre[tid];

    int d0 = lane * 4;
    unsigned long long acc[4][4] = {};    // [edge-pair][d] ; pair p = warp edges (2p, 2p+1)

    auto stage = [&](int buf, int kc) {
        float* base = sm + buf * BUF_STRIDE;
        float4* dwa = (float4*)base;
        float4* dwb = (float4*)(base + 2048);
        const float4* swa = g_wa + kc * KC * 32;
        const float4* swb = g_wb + kc * KC * 32;
        dwa[tid] = swa[tid]; dwa[tid + 256] = swa[tid + 256];
        dwb[tid] = swb[tid]; dwb[tid + 256] = swb[tid + 256];
        // t: 64 edges x 16 floats; one float4 per thread
        float* tb = base + OFF_TS;
        int eL = tid >> 2, qq = tid & 3;
        int e = eBase + eL;
        float4 tv = (e < E) ? *(const float4*)&T[(long long)e * EDIM + kc * KC + qq * 4]
                            : make_float4(0.f, 0.f, 0.f, 0.f);
        tb[(qq * 4 + 0) * 68 + eL] = tv.x;
        tb[(qq * 4 + 1) * 68 + eL] = tv.y;
        tb[(qq * 4 + 2) * 68 + eL] = tv.z;
        tb[(qq * 4 + 3) * 68 + eL] = tv.w;
    };

    stage(0, 0);
    __syncthreads();

    for (int kc = 0; kc < EDIM / KC; kc++) {
        int buf = kc & 1;
        if (kc + 1 < EDIM / KC) stage(buf ^ 1, kc + 1);

        const float* wa  = sm + buf * BUF_STRIDE;
        const float* wb  = sm + buf * BUF_STRIDE + 2048;
        const float* tsm = sm + buf * BUF_STRIDE + OFF_TS;
        #pragma unroll
        for (int j = 0; j < KC; j++) {
            ulonglong2 w01 = *(const ulonglong2*)&wa[j * 128 + d0];   // conflict-free 16B/lane
            ulonglong2 w23 = *(const ulonglong2*)&wb[j * 128 + d0];
            const ulonglong2* tp = (const ulonglong2*)&tsm[j * 68 + warp * 8];
            ulonglong2 tA = tp[0], tB = tp[1];                        // broadcast
            fma2(acc[0][0], tA.x, w01.x); fma2(acc[0][1], tA.x, w01.y); fma2(acc[0][2], tA.x, w23.x); fma2(acc[0][3], tA.x, w23.y);
            fma2(acc[1][0], tA.y, w01.x); fma2(acc[1][1], tA.y, w01.y); fma2(acc[1][2], tA.y, w23.x); fma2(acc[1][3], tA.y, w23.y);
            fma2(acc[2][0], tB.x, w01.x); fma2(acc[2][1], tB.x, w01.y); fma2(acc[2][2], tB.x, w23.x); fma2(acc[2][3], tB.x, w23.y);
            fma2(acc[3][0], tB.y, w01.x); fma2(acc[3][1], tB.y, w01.y); fma2(acc[3][2], tB.y, w23.x); fma2(acc[3][3], tB.y, w23.y);
        }
        __syncthreads();
    }

    int head = lane >> 2;
    const float* bsm = sm + OFF_BRE;
    float b0 = bsm[d0 + 0], b1 = bsm[d0 + 1], b2 = bsm[d0 + 2], b3 = bsm[d0 + 3];

    #pragma unroll
    for (int ei = 0; ei < 8; ei++) {
        int e = eBase + warp * 8 + ei;    // uniform within warp
        if (e >= E) continue;
        int nj = g_nj[e];
        int ni = g_ni[e];
        float4 q4 = *(const float4*)&g_q[ni * 128 + d0];
        float4 k4 = *(const float4*)&g_k[nj * 128 + d0];
        int p = ei >> 1;
        float lo0, hi0, lo1, hi1, lo2, hi2, lo3, hi3;
        unpack2(acc[p][0], lo0, hi0);
        unpack2(acc[p][1], lo1, hi1);
        unpack2(acc[p][2], lo2, hi2);
        unpack2(acc[p][3], lo3, hi3);
        float x0 = (ei & 1) ? hi0 : lo0;
        float x1 = (ei & 1) ? hi1 : lo1;
        float x2 = (ei & 1) ? hi2 : lo2;
        float x3 = (ei & 1) ? hi3 : lo3;
        x0 = siluf(x0 + b0); x1 = siluf(x1 + b1);
        x2 = siluf(x2 + b2); x3 = siluf(x3 + b3);
        float part = x0 * q4.x * k4.x + x1 * q4.y * k4.y
                   + x2 * q4.z * k4.z + x3 * q4.w * k4.w;
        part += __shfl_xor_sync(0xffffffffu, part, 1);
        part += __shfl_xor_sync(0xffffffffu, part, 2);
        if ((lane & 3) == 0) {
            float ex = __expf(fminf(part, 80.0f));  // shift-free softmax (logits bounded)
            g_a[e * 8 + head] = ex;
            atomicAdd(&g_s[ni * 8 + head], ex);
        }
    }
}

// ---------------- 6a) per-node P ----------------
__global__ __launch_bounds__(256)
void pmat_kernel(int Nn) {
    int tid = threadIdx.x;
    int h = tid >> 5;
    int o0 = (tid & 31) * 4;
    int n0 = blockIdx.x * 8;

    float acc[8][4];
    #pragma unroll
    for (int n = 0; n < 8; n++) { acc[n][0] = acc[n][1] = acc[n][2] = acc[n][3] = 0.0f; }

    #pragma unroll
    for (int dd = 0; dd < 16; dd++) {
        int d = h * 16 + dd;
        float4 w4 = *(const float4*)&g_WcT[d * OUTD + o0];
        #pragma unroll
        for (int n = 0; n < 8; n++) {
            int r = n0 + n;
            float vv = (r < Nn) ? g_v[r * OUTD + d] : 0.0f;
            acc[n][0] = fmaf(vv, w4.x, acc[n][0]);
            acc[n][1] = fmaf(vv, w4.y, acc[n][1]);
            acc[n][2] = fmaf(vv, w4.z, acc[n][2]);
            acc[n][3] = fmaf(vv, w4.w, acc[n][3]);
        }
    }
    #pragma unroll
    for (int n = 0; n < 8; n++) {
        int r = n0 + n;
        if (r < Nn) {
            *(float4*)&g_P[((r * 8 + h) * OUTD) + o0] =
                make_float4(acc[n][0], acc[n][1], acc[n][2], acc[n][3]);
        }
    }
}

// ---------------- 6b) invert sums ----------------
__global__ void sinv_kernel(int NH) {
    int i = blockIdx.x * blockDim.x + threadIdx.x;
    if (i < NH) g_s[i] = 0.25f / (g_s[i] + 1e-16f);
}

// ---------------- 7) output: block per node nj, P in registers, f32x2 accumulate ----------------
__global__ __launch_bounds__(256)
void out_kernel(const float* __restrict__ bc, float* __restrict__ outp, int E) {
    int n = blockIdx.x;
    int start = g_start[n], end = g_start[n + 1];
    if (start == end) return;
    int warp = threadIdx.x >> 5, lane = threadIdx.x & 31;
    int o0 = lane * 4;

    ulonglong2 P2[8];
    #pragma unroll
    for (int h = 0; h < 8; h++)
        P2[h] = *(const ulonglong2*)&g_P[((n * 8 + h) * OUTD) + o0];
    ulonglong2 bc2 = *(const ulonglong2*)&bc[o0];

    for (int i = start + warp; i < end; i += 8) {
        int e = g_elist[i];
        float w = 0.0f;
        if (lane < 8) {
            int ni = g_ni[e];
            w = g_a[e * 8 + lane] * g_s[ni * 8 + lane];
        }
        unsigned long long a0 = bc2.x, a1 = bc2.y;
        #pragma unroll
        for (int h = 0; h < 8; h++) {
            unsigned long long wh = pack2(__shfl_sync(0xffffffffu, w, h));
            fma2(a0, wh, P2[h].x);
            fma2(a1, wh, P2[h].y);
        }
        ulonglong2 res; res.x = a0; res.y = a1;
        *(ulonglong2*)&outp[(long long)e * 128 + o0] = res;
    }
}

// ---------------- host launcher ----------------
extern "C" void kernel_launch(void* const* d_in, const int* in_sizes, int n_in,
                              void* d_out, int out_size) {
    const float* h    = (const float*)d_in[0];
    const float* tij  = (const float*)d_in[1];
    const void*  eidx = d_in[2];
    const float* Wq   = (const float*)d_in[3];
    const float* bq   = (const float*)d_in[4];
    const float* Wk   = (const float*)d_in[5];
    const float* bk   = (const float*)d_in[6];
    const float* W1   = (const float*)d_in[7];
    const float* b1   = (const float*)d_in[8];
    const float* W2   = (const float*)d_in[9];
    const float* b2   = (const float*)d_in[10];
    const float* Wre  = (const float*)d_in[11];
    const float* bre  = (const float*)d_in[12];
    const float* Wc   = (const float*)d_in[13];
    const float* bc   = (const float*)d_in[14];

    int Nn = in_sizes[0] / DDIM;     // 10000
    int E  = in_sizes[1] / EDIM;     // 640000

    float *pq, *pk, *pu, *pv;
    cudaGetSymbolAddress((void**)&pq, g_q);
    cudaGetSymbolAddress((void**)&pk, g_k);
    cudaGetSymbolAddress((void**)&pu, g_u);
    cudaGetSymbolAddress((void**)&pv, g_v);

    static cudaStream_t s1 = nullptr, s2 = nullptr;
    static cudaEvent_t evFork = nullptr, evQK = nullptr, evB = nullptr,
                       evConv = nullptr, evScat = nullptr;
    if (!s1) {
        cudaFuncSetAttribute(edge_logits_kernel, cudaFuncAttributeMaxDynamicSharedMemorySize, EL_SMEM);
        cudaStreamCreateWithFlags(&s1, cudaStreamNonBlocking);
        cudaStreamCreateWithFlags(&s2, cudaStreamNonBlocking);
        cudaEventCreateWithFlags(&evFork, cudaEventDisableTiming);
        cudaEventCreateWithFlags(&evQK,   cudaEventDisableTiming);
        cudaEventCreateWithFlags(&evB,    cudaEventDisableTiming);
        cudaEventCreateWithFlags(&evConv, cudaEventDisableTiming);
        cudaEventCreateWithFlags(&evScat, cudaEventDisableTiming);
    }

    // launch #1: init (+ index-width detect)
    {
        int total = Nn * HDS;
        if (total < OUTD * OUTD) total = OUTD * OUTD;
        if (total < Nn) total = Nn;
        init_kernel<<<(total + 255) / 256, 256>>>(Wc, (const unsigned*)eidx, Nn * HDS, Nn);
    }

    cudaEventRecord(evFork, 0);
    cudaStreamWaitEvent(s1, evFork, 0);

    // launch #2: gemm3 (q,k,u) on s1
    int gb = (Nn + 31) / 32;
    {
        dim3 grid(gb, 3);
        gemm3_kernel<<<grid, 256, 0, s1>>>(h, Wq, bq, Wk, bk, W1, b1, pq, pk, pu, Nn);
    }
    cudaEventRecord(evQK, s1);

    // launch #3: convert + hist + wdup planes on stream 0
    {
        int eBlocks = (E + 255) / 256;
        convert_hist_wdup_kernel<<<eBlocks + 16, 256>>>(eidx, Wre, E, eBlocks);
    }
    cudaEventRecord(evConv, 0);

    // launch #4: edge_logits (ncu slot)
    cudaStreamWaitEvent(0, evQK, 0);
    edge_logits_kernel<<<(E + ELB - 1) / ELB, 256, EL_SMEM>>>(tij, bre, E);

    // side branches
    gemm_kernel<<<gb, 256, 0, s1>>>(pu, W2, b2, pv, Nn);
    pmat_kernel<<<(Nn + 7) / 8, 256, 0, s1>>>(Nn);
    cudaEventRecord(evB, s1);

    cudaStreamWaitEvent(s2, evConv, 0);
    scan_kernel<<<1, 1024, 0, s2>>>(Nn);
    scatter_kernel<<<(E + 255) / 256, 256, 0, s2>>>(E);
    cudaEventRecord(evScat, s2);

    // critical path
    sinv_kernel<<<(Nn * HDS + 255) / 256, 256>>>(Nn * HDS);

    cudaStreamWaitEvent(0, evB, 0);
    cudaStreamWaitEvent(0, evScat, 0);
    out_kernel<<<Nn, 256>>>(bc, (float*)d_out, E);
}

// round 14
// speedup vs baseline: 1.0317x; 1.0317x over previous
#include <cuda_runtime.h>
#include <cstdint>

// ---------------- problem constants ----------------
#define NMAX 10000
#define EMAX 640000
#define DDIM 128
#define EDIM 64
#define HDS  8
#define OUTD 128

// ---------------- device scratch ----------------
__device__ __align__(16) float g_q[NMAX * DDIM];
__device__ __align__(16) float g_k[NMAX * DDIM];
__device__ __align__(16) float g_u[NMAX * OUTD];
__device__ __align__(16) float g_v[NMAX * OUTD];
__device__ __align__(16) float g_P[NMAX * HDS * OUTD];
__device__ __align__(16) float g_a[EMAX * HDS];     // exp(logit), by ORIGINAL edge id
__device__ __align__(16) float g_s[NMAX * HDS];     // segment sums -> 0.25/(s+eps)
__device__ __align__(16) float g_WcT[OUTD * OUTD];
// duplicated Wre, split into two conflict-free planes
__device__ __align__(16) float4 g_wa[EDIM * 32];
__device__ __align__(16) float4 g_wb[EDIM * 32];
__device__ int g_is64;
__device__ int g_nj[EMAX];
__device__ int g_ni[EMAX];
__device__ int g_cnt[NMAX];
__device__ int g_start[NMAX + 1];
__device__ int g_off[NMAX];
__device__ int g_elist[EMAX];

// ---------------- helpers ----------------
__device__ __forceinline__ unsigned long long pack2(float x) {
    unsigned long long r; unsigned u = __float_as_uint(x);
    asm("mov.b64 %0, {%1, %1};" : "=l"(r) : "r"(u));
    return r;
}
__device__ __forceinline__ void fma2(unsigned long long& d, unsigned long long a, unsigned long long b) {
    asm("fma.rn.f32x2 %0, %1, %2, %0;" : "+l"(d) : "l"(a), "l"(b));
}
__device__ __forceinline__ void unpack2(unsigned long long v, float& x, float& y) {
    unsigned a, b;
    asm("mov.b64 {%0, %1}, %2;" : "=r"(a), "=r"(b) : "l"(v));
    x = __uint_as_float(a); y = __uint_as_float(b);
}
// precise-ish silu for node GEMM path (count negligible there)
__device__ __forceinline__ float siluf(float x) { return __fdividef(x, 1.0f + __expf(-x)); }
// 1-MUFU silu via tanh: silu(x) = x * 0.5 * (1 + tanh(x/2))
__device__ __forceinline__ float silu_tanh(float x) {
    float t;
    float hx = 0.5f * x;
    asm("tanh.approx.f32 %0, %1;" : "=f"(t) : "f"(hx));
    return fmaf(hx, t, hx);
}
__device__ __forceinline__ int load_idx(const void* eidx, int is64, long long pos) {
    return is64 ? (int)((const long long*)eidx)[pos] : ((const int*)eidx)[pos];
}

// ---------------- 1) init (+ index-width detection in block 0) ----------------
__global__ void init_kernel(const float* __restrict__ Wc, const unsigned* __restrict__ ew,
                            int NH, int Nn) {
    if (blockIdx.x == 0) {
        __shared__ int any;
        if (threadIdx.x == 0) any = 0;
        __syncthreads();
        #pragma unroll
        for (int k = 0; k < 4; k++) {
            int i = threadIdx.x + k * 256;
            if (ew[i * 2 + 1] != 0u) any = 1;
        }
        __syncthreads();
        if (threadIdx.x == 0) g_is64 = (any == 0) ? 1 : 0;
    }
    int i = blockIdx.x * blockDim.x + threadIdx.x;
    if (i < NH) g_s[i] = 0.0f;
    if (i < Nn) g_cnt[i] = 0;
    if (i < OUTD * OUTD) {
        int o = i >> 7, d = i & 127;
        g_WcT[d * OUTD + o] = Wc[i];
    }
}

// ---------------- 2) convert indices + histogram, fused with Wre plane prep ----------------
__global__ void convert_hist_wdup_kernel(const void* __restrict__ eidx,
                                         const float* __restrict__ Wre,
                                         int E, int eBlocks) {
    if (blockIdx.x >= eBlocks) {
        int idx = (blockIdx.x - eBlocks) * blockDim.x + threadIdx.x;  // 0..4095
        if (idx < EDIM * 32 * 2) {
            int which = idx >> 11;
            int rem = idx & 2047;
            int j = rem >> 5, l = rem & 31;
            int d0 = l * 4 + which * 2;
            float v0 = Wre[d0 * EDIM + j];
            float v1 = Wre[(d0 + 1) * EDIM + j];
            float4 out = make_float4(v0, v0, v1, v1);
            if (which == 0) g_wa[j * 32 + l] = out;
            else            g_wb[j * 32 + l] = out;
        }
        return;
    }
    int e = blockIdx.x * blockDim.x + threadIdx.x;
    if (e >= E) return;
    int is64 = g_is64;
    int nj = load_idx(eidx, is64, e);
    int ni = load_idx(eidx, is64, (long long)E + e);
    g_nj[e] = nj;
    g_ni[e] = ni;
    atomicAdd(&g_cnt[nj], 1);
}

// ---------------- 3) node GEMMs (32-row tile, 4x4 reg block) ----------------
#define PADW 132
#define PADA 36
__global__ __launch_bounds__(256)
void gemm3_kernel(const float* __restrict__ A,
                  const float* __restrict__ W0, const float* __restrict__ B0,
                  const float* __restrict__ W1p, const float* __restrict__ B1,
                  const float* __restrict__ W2p, const float* __restrict__ B2,
                  float* __restrict__ C0, float* __restrict__ C1, float* __restrict__ C2,
                  int M) {
    const float* W = (blockIdx.y == 0) ? W0 : (blockIdx.y == 1) ? W1p : W2p;
    const float* bias = (blockIdx.y == 0) ? B0 : (blockIdx.y == 1) ? B1 : B2;
    float* C = (blockIdx.y == 0) ? C0 : (blockIdx.y == 1) ? C1 : C2;
    int act = (blockIdx.y == 2);

    __shared__ float wsm[64 * PADW];
    __shared__ float asmv[64 * PADA];
    __shared__ float bsm[128];

    int tid = threadIdx.x;
    int row0 = blockIdx.x * 32;
    int nIdx = tid & 31, mIdx = tid >> 5;
    int n0 = nIdx * 4, m0 = mIdx * 4;
    if (tid < 128) bsm[tid] = bias[tid];

    unsigned long long acc2[4][2] = {};
    for (int kt = 0; kt < DDIM; kt += 64) {
        for (int idx = tid; idx < 128 * 64; idx += 256) {
            int o = idx >> 6, jj = idx & 63;
            wsm[jj * PADW + o] = W[o * DDIM + kt + jj];
        }
        for (int idx = tid; idx < 32 * 64; idx += 256) {
            int m = idx >> 6, jj = idx & 63;
            int r = row0 + m;
            asmv[jj * PADA + m] = (r < M) ? A[r * DDIM + kt + jj] : 0.0f;
        }
        __syncthreads();
        #pragma unroll 16
        for (int j = 0; j < 64; j++) {
            ulonglong2 wv = *(const ulonglong2*)&wsm[j * PADW + n0];
            float4 av = *(const float4*)&asmv[j * PADA + m0];
            unsigned long long a0 = pack2(av.x), a1 = pack2(av.y),
                               a2 = pack2(av.z), a3 = pack2(av.w);
            fma2(acc2[0][0], a0, wv.x); fma2(acc2[0][1], a0, wv.y);
            fma2(acc2[1][0], a1, wv.x); fma2(acc2[1][1], a1, wv.y);
            fma2(acc2[2][0], a2, wv.x); fma2(acc2[2][1], a2, wv.y);
            fma2(acc2[3][0], a3, wv.x); fma2(acc2[3][1], a3, wv.y);
        }
        __syncthreads();
    }
    #pragma unroll
    for (int mi = 0; mi < 4; mi++) {
        int r = row0 + m0 + mi;
        if (r < M) {
            float v0, v1, v2, v3;
            unpack2(acc2[mi][0], v0, v1);
            unpack2(acc2[mi][1], v2, v3);
            v0 += bsm[n0 + 0]; v1 += bsm[n0 + 1]; v2 += bsm[n0 + 2]; v3 += bsm[n0 + 3];
            if (act) { v0 = siluf(v0); v1 = siluf(v1); v2 = siluf(v2); v3 = siluf(v3); }
            *(float4*)&C[r * 128 + n0] = make_float4(v0, v1, v2, v3);
        }
    }
}

__global__ __launch_bounds__(256)
void gemm_kernel(const float* __restrict__ A, const float* __restrict__ W,
                 const float* __restrict__ bias, float* __restrict__ C, int M) {
    __shared__ float wsm[64 * PADW];
    __shared__ float asmv[64 * PADA];
    __shared__ float bsm[128];

    int tid = threadIdx.x;
    int row0 = blockIdx.x * 32;
    int nIdx = tid & 31, mIdx = tid >> 5;
    int n0 = nIdx * 4, m0 = mIdx * 4;
    if (tid < 128) bsm[tid] = bias[tid];

    unsigned long long acc2[4][2] = {};
    for (int kt = 0; kt < OUTD; kt += 64) {
        for (int idx = tid; idx < 128 * 64; idx += 256) {
            int o = idx >> 6, jj = idx & 63;
            wsm[jj * PADW + o] = W[o * OUTD + kt + jj];
        }
        for (int idx = tid; idx < 32 * 64; idx += 256) {
            int m = idx >> 6, jj = idx & 63;
            int r = row0 + m;
            asmv[jj * PADA + m] = (r < M) ? A[r * OUTD + kt + jj] : 0.0f;
        }
        __syncthreads();
        #pragma unroll 16
        for (int j = 0; j < 64; j++) {
            ulonglong2 wv = *(const ulonglong2*)&wsm[j * PADW + n0];
            float4 av = *(const float4*)&asmv[j * PADA + m0];
            unsigned long long a0 = pack2(av.x), a1 = pack2(av.y),
                               a2 = pack2(av.z), a3 = pack2(av.w);
            fma2(acc2[0][0], a0, wv.x); fma2(acc2[0][1], a0, wv.y);
            fma2(acc2[1][0], a1, wv.x); fma2(acc2[1][1], a1, wv.y);
            fma2(acc2[2][0], a2, wv.x); fma2(acc2[2][1], a2, wv.y);
            fma2(acc2[3][0], a3, wv.x); fma2(acc2[3][1], a3, wv.y);
        }
        __syncthreads();
    }
    #pragma unroll
    for (int mi = 0; mi < 4; mi++) {
        int r = row0 + m0 + mi;
        if (r < M) {
            float v0, v1, v2, v3;
            unpack2(acc2[mi][0], v0, v1);
            unpack2(acc2[mi][1], v2, v3);
            v0 += bsm[n0 + 0]; v1 += bsm[n0 + 1]; v2 += bsm[n0 + 2]; v3 += bsm[n0 + 3];
            *(float4*)&C[r * 128 + n0] = make_float4(v0, v1, v2, v3);
        }
    }
}

// ---------------- 4) sort: scan + scatter ----------------
__global__ __launch_bounds__(1024)
void scan_kernel(int Nn) {
    __shared__ int part[1024];
    int t = threadIdx.x;
    int chunk = (Nn + 1023) >> 10;
    int base = t * chunk;
    int local[16];
    int sum = 0;
    for (int i = 0; i < chunk; i++) {
        int idx = base + i;
        int c = (idx < Nn) ? g_cnt[idx] : 0;
        local[i] = sum; sum += c;
    }
    part[t] = sum;
    __syncthreads();
    for (int off = 1; off < 1024; off <<= 1) {
        int v = (t >= off) ? part[t - off] : 0;
        __syncthreads();
        part[t] += v;
        __syncthreads();
    }
    int pre = (t > 0) ? part[t - 1] : 0;
    for (int i = 0; i < chunk; i++) {
        int idx = base + i;
        if (idx < Nn) { int s0 = pre + local[i]; g_start[idx] = s0; g_off[idx] = s0; }
    }
    if (t == 0) g_start[Nn] = part[1023];
}

__global__ void scatter_kernel(int E) {
    int e = blockIdx.x * blockDim.x + threadIdx.x;
    if (e >= E) return;
    int nj = g_nj[e];
    int pos = atomicAdd(&g_off[nj], 1);
    g_elist[pos] = e;
}

// ---------------- 5) edge logits: double-buffered, conflict-free planes, tanh-silu ----------------
#define ELB 128
#define KC 16
#define BUF_STRIDE 6208
#define OFF_TS 4096
#define OFF_BRE 12416
#define EL_SMEM ((12416 + 128) * 4)  // 50176 bytes

__global__ __launch_bounds__(256, 2)
void edge_logits_kernel(const float* __restrict__ T, const float* __restrict__ bre, int E) {
    extern __shared__ float sm[];
    int tid = threadIdx.x;
    int warp = tid >> 5, lane = tid & 31;
    int eBase = blockIdx.x * ELB;
    if (tid < 128) sm[OFF_BRE + tid] = bre[tid];

    int d0 = lane * 4;
    unsigned long long acc[8][4] = {};    // [edge-pair][d]

    auto stage = [&](int buf, int kc) {
        float* base = sm + buf * BUF_STRIDE;
        float4* dwa = (float4*)base;
        float4* dwb = (float4*)(base + 2048);
        const float4* swa = g_wa + kc * KC * 32;
        const float4* swb = g_wb + kc * KC * 32;
        dwa[tid] = swa[tid]; dwa[tid + 256] = swa[tid + 256];
        dwb[tid] = swb[tid]; dwb[tid + 256] = swb[tid + 256];
        float* tb = base + OFF_TS;
        #pragma unroll
        for (int idx = tid; idx < ELB * KC; idx += 256) {
            int jj = idx & (KC - 1), eL = idx >> 4;
            int e = eBase + eL;
            tb[jj * 132 + eL] = (e < E) ? T[(long long)e * EDIM + kc * KC + jj] : 0.0f;
        }
    };

    stage(0, 0);
    __syncthreads();

    for (int kc = 0; kc < EDIM / KC; kc++) {
        int buf = kc & 1;
        if (kc + 1 < EDIM / KC) stage(buf ^ 1, kc + 1);

        const float* wa  = sm + buf * BUF_STRIDE;
        const float* wb  = sm + buf * BUF_STRIDE + 2048;
        const float* tsm = sm + buf * BUF_STRIDE + OFF_TS;
        #pragma unroll
        for (int j = 0; j < KC; j++) {
            ulonglong2 w01 = *(const ulonglong2*)&wa[j * 128 + d0];
            ulonglong2 w23 = *(const ulonglong2*)&wb[j * 128 + d0];
            const ulonglong2* tp = (const ulonglong2*)&tsm[j * 132 + warp * 16];
            ulonglong2 tA = tp[0], tB = tp[1], tC = tp[2], tD = tp[3];
            fma2(acc[0][0], tA.x, w01.x); fma2(acc[0][1], tA.x, w01.y); fma2(acc[0][2], tA.x, w23.x); fma2(acc[0][3], tA.x, w23.y);
            fma2(acc[1][0], tA.y, w01.x); fma2(acc[1][1], tA.y, w01.y); fma2(acc[1][2], tA.y, w23.x); fma2(acc[1][3], tA.y, w23.y);
            fma2(acc[2][0], tB.x, w01.x); fma2(acc[2][1], tB.x, w01.y); fma2(acc[2][2], tB.x, w23.x); fma2(acc[2][3], tB.x, w23.y);
            fma2(acc[3][0], tB.y, w01.x); fma2(acc[3][1], tB.y, w01.y); fma2(acc[3][2], tB.y, w23.x); fma2(acc[3][3], tB.y, w23.y);
            fma2(acc[4][0], tC.x, w01.x); fma2(acc[4][1], tC.x, w01.y); fma2(acc[4][2], tC.x, w23.x); fma2(acc[4][3], tC.x, w23.y);
            fma2(acc[5][0], tC.y, w01.x); fma2(acc[5][1], tC.y, w01.y); fma2(acc[5][2], tC.y, w23.x); fma2(acc[5][3], tC.y, w23.y);
            fma2(acc[6][0], tD.x, w01.x); fma2(acc[6][1], tD.x, w01.y); fma2(acc[6][2], tD.x, w23.x); fma2(acc[6][3], tD.x, w23.y);
            fma2(acc[7][0], tD.y, w01.x); fma2(acc[7][1], tD.y, w01.y); fma2(acc[7][2], tD.y, w23.x); fma2(acc[7][3], tD.y, w23.y);
        }
        __syncthreads();
    }

    int head = lane >> 2;
    const float* bsm = sm + OFF_BRE;
    float b0 = bsm[d0 + 0], b1 = bsm[d0 + 1], b2 = bsm[d0 + 2], b3 = bsm[d0 + 3];

    #pragma unroll
    for (int ei = 0; ei < 16; ei++) {
        int e = eBase + warp * 16 + ei;
        if (e >= E) continue;
        int nj = g_nj[e];
        int ni = g_ni[e];
        float4 q4 = *(const float4*)&g_q[ni * 128 + d0];
        float4 k4 = *(const float4*)&g_k[nj * 128 + d0];
        int p = ei >> 1;
        float lo0, hi0, lo1, hi1, lo2, hi2, lo3, hi3;
        unpack2(acc[p][0], lo0, hi0);
        unpack2(acc[p][1], lo1, hi1);
        unpack2(acc[p][2], lo2, hi2);
        unpack2(acc[p][3], lo3, hi3);
        float x0 = (ei & 1) ? hi0 : lo0;
        float x1 = (ei & 1) ? hi1 : lo1;
        float x2 = (ei & 1) ? hi2 : lo2;
        float x3 = (ei & 1) ? hi3 : lo3;
        x0 = silu_tanh(x0 + b0); x1 = silu_tanh(x1 + b1);
        x2 = silu_tanh(x2 + b2); x3 = silu_tanh(x3 + b3);
        float part = x0 * q4.x * k4.x + x1 * q4.y * k4.y
                   + x2 * q4.z * k4.z + x3 * q4.w * k4.w;
        part += __shfl_xor_sync(0xffffffffu, part, 1);
        part += __shfl_xor_sync(0xffffffffu, part, 2);
        if ((lane & 3) == 0) {
            float ex = __expf(fminf(part, 80.0f));  // shift-free softmax (logits bounded)
            g_a[e * 8 + head] = ex;
            atomicAdd(&g_s[ni * 8 + head], ex);
        }
    }
}

// ---------------- 6a) per-node P ----------------
__global__ __launch_bounds__(256)
void pmat_kernel(int Nn) {
    int tid = threadIdx.x;
    int h = tid >> 5;
    int o0 = (tid & 31) * 4;
    int n0 = blockIdx.x * 8;

    float acc[8][4];
    #pragma unroll
    for (int n = 0; n < 8; n++) { acc[n][0] = acc[n][1] = acc[n][2] = acc[n][3] = 0.0f; }

    #pragma unroll
    for (int dd = 0; dd < 16; dd++) {
        int d = h * 16 + dd;
        float4 w4 = *(const float4*)&g_WcT[d * OUTD + o0];
        #pragma unroll
        for (int n = 0; n < 8; n++) {
            int r = n0 + n;
            float vv = (r < Nn) ? g_v[r * OUTD + d] : 0.0f;
            acc[n][0] = fmaf(vv, w4.x, acc[n][0]);
            acc[n][1] = fmaf(vv, w4.y, acc[n][1]);
            acc[n][2] = fmaf(vv, w4.z, acc[n][2]);
            acc[n][3] = fmaf(vv, w4.w, acc[n][3]);
        }
    }
    #pragma unroll
    for (int n = 0; n < 8; n++) {
        int r = n0 + n;
        if (r < Nn) {
            *(float4*)&g_P[((r * 8 + h) * OUTD) + o0] =
                make_float4(acc[n][0], acc[n][1], acc[n][2], acc[n][3]);
        }
    }
}

// ---------------- 6b) invert sums ----------------
__global__ void sinv_kernel(int NH) {
    int i = blockIdx.x * blockDim.x + threadIdx.x;
    if (i < NH) g_s[i] = 0.25f / (g_s[i] + 1e-16f);
}

// ---------------- 7) output: block per node nj, P in registers, f32x2 accumulate ----------------
__global__ __launch_bounds__(256)
void out_kernel(const float* __restrict__ bc, float* __restrict__ outp, int E) {
    int n = blockIdx.x;
    int start = g_start[n], end = g_start[n + 1];
    if (start == end) return;
    int warp = threadIdx.x >> 5, lane = threadIdx.x & 31;
    int o0 = lane * 4;

    ulonglong2 P2[8];
    #pragma unroll
    for (int h = 0; h < 8; h++)
        P2[h] = *(const ulonglong2*)&g_P[((n * 8 + h) * OUTD) + o0];
    ulonglong2 bc2 = *(const ulonglong2*)&bc[o0];

    for (int i = start + warp; i < end; i += 8) {
        int e = g_elist[i];
        float w = 0.0f;
        if (lane < 8) {
            int ni = g_ni[e];
            w = g_a[e * 8 + lane] * g_s[ni * 8 + lane];
        }
        unsigned long long a0 = bc2.x, a1 = bc2.y;
        #pragma unroll
        for (int h = 0; h < 8; h++) {
            unsigned long long wh = pack2(__shfl_sync(0xffffffffu, w, h));
            fma2(a0, wh, P2[h].x);
            fma2(a1, wh, P2[h].y);
        }
        ulonglong2 res; res.x = a0; res.y = a1;
        *(ulonglong2*)&outp[(long long)e * 128 + o0] = res;
    }
}

// ---------------- host launcher ----------------
extern "C" void kernel_launch(void* const* d_in, const int* in_sizes, int n_in,
                              void* d_out, int out_size) {
    const float* h    = (const float*)d_in[0];
    const float* tij  = (const float*)d_in[1];
    const void*  eidx = d_in[2];
    const float* Wq   = (const float*)d_in[3];
    const float* bq   = (const float*)d_in[4];
    const float* Wk   = (const float*)d_in[5];
    const float* bk   = (const float*)d_in[6];
    const float* W1   = (const float*)d_in[7];
    const float* b1   = (const float*)d_in[8];
    const float* W2   = (const float*)d_in[9];
    const float* b2   = (const float*)d_in[10];
    const float* Wre  = (const float*)d_in[11];
    const float* bre  = (const float*)d_in[12];
    const float* Wc   = (const float*)d_in[13];
    const float* bc   = (const float*)d_in[14];

    int Nn = in_sizes[0] / DDIM;     // 10000
    int E  = in_sizes[1] / EDIM;     // 640000

    float *pq, *pk, *pu, *pv;
    cudaGetSymbolAddress((void**)&pq, g_q);
    cudaGetSymbolAddress((void**)&pk, g_k);
    cudaGetSymbolAddress((void**)&pu, g_u);
    cudaGetSymbolAddress((void**)&pv, g_v);

    static cudaStream_t s1 = nullptr, s2 = nullptr;
    static cudaEvent_t evFork = nullptr, evQK = nullptr, evB = nullptr,
                       evConv = nullptr, evScat = nullptr;
    if (!s1) {
        cudaFuncSetAttribute(edge_logits_kernel, cudaFuncAttributeMaxDynamicSharedMemorySize, EL_SMEM);
        cudaStreamCreateWithFlags(&s1, cudaStreamNonBlocking);
        cudaStreamCreateWithFlags(&s2, cudaStreamNonBlocking);
        cudaEventCreateWithFlags(&evFork, cudaEventDisableTiming);
        cudaEventCreateWithFlags(&evQK,   cudaEventDisableTiming);
        cudaEventCreateWithFlags(&evB,    cudaEventDisableTiming);
        cudaEventCreateWithFlags(&evConv, cudaEventDisableTiming);
        cudaEventCreateWithFlags(&evScat, cudaEventDisableTiming);
    }

    // launch #1: init (+ index-width detect)
    {
        int total = Nn * HDS;
        if (total < OUTD * OUTD) total = OUTD * OUTD;
        if (total < Nn) total = Nn;
        init_kernel<<<(total + 255) / 256, 256>>>(Wc, (const unsigned*)eidx, Nn * HDS, Nn);
    }

    cudaEventRecord(evFork, 0);
    cudaStreamWaitEvent(s1, evFork, 0);

    // launch #2: gemm3 (q,k,u) on s1
    int gb = (Nn + 31) / 32;
    {
        dim3 grid(gb, 3);
        gemm3_kernel<<<grid, 256, 0, s1>>>(h, Wq, bq, Wk, bk, W1, b1, pq, pk, pu, Nn);
    }
    cudaEventRecord(evQK, s1);

    // launch #3: convert + hist + wdup planes on stream 0
    {
        int eBlocks = (E + 255) / 256;
        convert_hist_wdup_kernel<<<eBlocks + 16, 256>>>(eidx, Wre, E, eBlocks);
    }
    cudaEventRecord(evConv, 0);

    // launch #4: edge_logits (ncu slot)
    cudaStreamWaitEvent(0, evQK, 0);
    edge_logits_kernel<<<(E + ELB - 1) / ELB, 256, EL_SMEM>>>(tij, bre, E);

    // side branches
    gemm_kernel<<<gb, 256, 0, s1>>>(pu, W2, b2, pv, Nn);
    pmat_kernel<<<(Nn + 7) / 8, 256, 0, s1>>>(Nn);
    cudaEventRecord(evB, s1);

    cudaStreamWaitEvent(s2, evConv, 0);
    scan_kernel<<<1, 1024, 0, s2>>>(Nn);
    scatter_kernel<<<(E + 255) / 256, 256, 0, s2>>>(E);
    cudaEventRecord(evScat, s2);

    // critical path
    sinv_kernel<<<(Nn * HDS + 255) / 256, 256>>>(Nn * HDS);

    cudaStreamWaitEvent(0, evB, 0);
    cudaStreamWaitEvent(0, evScat, 0);
    out_kernel<<<Nn, 256>>>(bc, (float*)d_out, E);
}

// round 15
// speedup vs baseline: 1.0545x; 1.0221x over previous
#include <cuda_runtime.h>
#include <cstdint>

// ---------------- problem constants ----------------
#define NMAX 10000
#define EMAX 640000
#define DDIM 128
#define EDIM 64
#define HDS  8
#define OUTD 128

// ---------------- device scratch ----------------
__device__ __align__(16) float g_q[NMAX * DDIM];
__device__ __align__(16) float g_k[NMAX * DDIM];
__device__ __align__(16) float g_u[NMAX * OUTD];
__device__ __align__(16) float g_v[NMAX * OUTD];
__device__ __align__(16) float g_P[NMAX * HDS * OUTD];
__device__ __align__(16) float g_a[EMAX * HDS];
__device__ __align__(16) float g_s[NMAX * HDS];
__device__ __align__(16) float g_WcT[OUTD * OUTD];
// duplicated Wre, two conflict-free planes (float4 per lane)
__device__ __align__(16) float4 g_wa[EDIM * 32];
__device__ __align__(16) float4 g_wb[EDIM * 32];
__device__ int g_is64;
__device__ int g_nj[EMAX];
__device__ int g_ni[EMAX];
__device__ int g_cnt[NMAX];
__device__ int g_start[NMAX + 1];
__device__ int g_off[NMAX];
__device__ int g_elist[EMAX];

// ---------------- helpers ----------------
__device__ __forceinline__ unsigned long long pack2(float x) {
    unsigned long long r; unsigned u = __float_as_uint(x);
    asm("mov.b64 %0, {%1, %1};" : "=l"(r) : "r"(u));
    return r;
}
__device__ __forceinline__ void fma2(unsigned long long& d, unsigned long long a, unsigned long long b) {
    asm("fma.rn.f32x2 %0, %1, %2, %0;" : "+l"(d) : "l"(a), "l"(b));
}
__device__ __forceinline__ void unpack2(unsigned long long v, float& x, float& y) {
    unsigned a, b;
    asm("mov.b64 {%0, %1}, %2;" : "=r"(a), "=r"(b) : "l"(v));
    x = __uint_as_float(a); y = __uint_as_float(b);
}
__device__ __forceinline__ float siluf(float x) { return __fdividef(x, 1.0f + __expf(-x)); }
__device__ __forceinline__ float silu_tanh(float x) {
    float t;
    float hx = 0.5f * x;
    asm("tanh.approx.f32 %0, %1;" : "=f"(t) : "f"(hx));
    return fmaf(hx, t, hx);
}
__device__ __forceinline__ int load_idx(const void* eidx, int is64, long long pos) {
    return is64 ? (int)((const long long*)eidx)[pos] : ((const int*)eidx)[pos];
}
__device__ __forceinline__ uint32_t smem_u32(const void* p) {
    uint32_t a;
    asm("{ .reg .u64 t; cvta.to.shared.u64 t, %1; cvt.u32.u64 %0, t; }" : "=r"(a) : "l"(p));
    return a;
}
#define CP_ASYNC16(dst_u32, src_ptr) \
    asm volatile("cp.async.ca.shared.global [%0], [%1], 16;" :: "r"(dst_u32), "l"(src_ptr))
#define CP_COMMIT() asm volatile("cp.async.commit_group;" ::: "memory")
#define CP_WAIT0()  asm volatile("cp.async.wait_group 0;" ::: "memory")

// ---------------- 1) init (+ index-width detection in block 0) ----------------
__global__ void init_kernel(const float* __restrict__ Wc, const unsigned* __restrict__ ew,
                            int NH, int Nn) {
    if (blockIdx.x == 0) {
        __shared__ int any;
        if (threadIdx.x == 0) any = 0;
        __syncthreads();
        #pragma unroll
        for (int k = 0; k < 4; k++) {
            int i = threadIdx.x + k * 256;
            if (ew[i * 2 + 1] != 0u) any = 1;
        }
        __syncthreads();
        if (threadIdx.x == 0) g_is64 = (any == 0) ? 1 : 0;
    }
    int i = blockIdx.x * blockDim.x + threadIdx.x;
    if (i < NH) g_s[i] = 0.0f;
    if (i < Nn) g_cnt[i] = 0;
    if (i < OUTD * OUTD) {
        int o = i >> 7, d = i & 127;
        g_WcT[d * OUTD + o] = Wc[i];
    }
}

// ---------------- 2) convert indices + histogram, fused with Wre plane prep ----------------
__global__ void convert_hist_wdup_kernel(const void* __restrict__ eidx,
                                         const float* __restrict__ Wre,
                                         int E, int eBlocks) {
    if (blockIdx.x >= eBlocks) {
        int idx = (blockIdx.x - eBlocks) * blockDim.x + threadIdx.x;
        if (idx < EDIM * 32 * 2) {
            int which = idx >> 11;
            int rem = idx & 2047;
            int j = rem >> 5, l = rem & 31;
            int d0 = l * 4 + which * 2;
            float v0 = Wre[d0 * EDIM + j];
            float v1 = Wre[(d0 + 1) * EDIM + j];
            float4 out = make_float4(v0, v0, v1, v1);
            if (which == 0) g_wa[j * 32 + l] = out;
            else            g_wb[j * 32 + l] = out;
        }
        return;
    }
    int e = blockIdx.x * blockDim.x + threadIdx.x;
    if (e >= E) return;
    int is64 = g_is64;
    int nj = load_idx(eidx, is64, e);
    int ni = load_idx(eidx, is64, (long long)E + e);
    g_nj[e] = nj;
    g_ni[e] = ni;
    atomicAdd(&g_cnt[nj], 1);
}

// ---------------- 3) node GEMMs (32-row tile, 4x4 reg block) ----------------
#define PADW 132
#define PADA 36
__global__ __launch_bounds__(256)
void gemm3_kernel(const float* __restrict__ A,
                  const float* __restrict__ W0, const float* __restrict__ B0,
                  const float* __restrict__ W1p, const float* __restrict__ B1,
                  const float* __restrict__ W2p, const float* __restrict__ B2,
                  float* __restrict__ C0, float* __restrict__ C1, float* __restrict__ C2,
                  int M) {
    const float* W = (blockIdx.y == 0) ? W0 : (blockIdx.y == 1) ? W1p : W2p;
    const float* bias = (blockIdx.y == 0) ? B0 : (blockIdx.y == 1) ? B1 : B2;
    float* C = (blockIdx.y == 0) ? C0 : (blockIdx.y == 1) ? C1 : C2;
    int act = (blockIdx.y == 2);

    __shared__ float wsm[64 * PADW];
    __shared__ float asmv[64 * PADA];
    __shared__ float bsm[128];

    int tid = threadIdx.x;
    int row0 = blockIdx.x * 32;
    int nIdx = tid & 31, mIdx = tid >> 5;
    int n0 = nIdx * 4, m0 = mIdx * 4;
    if (tid < 128) bsm[tid] = bias[tid];

    unsigned long long acc2[4][2] = {};
    for (int kt = 0; kt < DDIM; kt += 64) {
        for (int idx = tid; idx < 128 * 64; idx += 256) {
            int o = idx >> 6, jj = idx & 63;
            wsm[jj * PADW + o] = W[o * DDIM + kt + jj];
        }
        for (int idx = tid; idx < 32 * 64; idx += 256) {
            int m = idx >> 6, jj = idx & 63;
            int r = row0 + m;
            asmv[jj * PADA + m] = (r < M) ? A[r * DDIM + kt + jj] : 0.0f;
        }
        __syncthreads();
        #pragma unroll 16
        for (int j = 0; j < 64; j++) {
            ulonglong2 wv = *(const ulonglong2*)&wsm[j * PADW + n0];
            float4 av = *(const float4*)&asmv[j * PADA + m0];
            unsigned long long a0 = pack2(av.x), a1 = pack2(av.y),
                               a2 = pack2(av.z), a3 = pack2(av.w);
            fma2(acc2[0][0], a0, wv.x); fma2(acc2[0][1], a0, wv.y);
            fma2(acc2[1][0], a1, wv.x); fma2(acc2[1][1], a1, wv.y);
            fma2(acc2[2][0], a2, wv.x); fma2(acc2[2][1], a2, wv.y);
            fma2(acc2[3][0], a3, wv.x); fma2(acc2[3][1], a3, wv.y);
        }
        __syncthreads();
    }
    #pragma unroll
    for (int mi = 0; mi < 4; mi++) {
        int r = row0 + m0 + mi;
        if (r < M) {
            float v0, v1, v2, v3;
            unpack2(acc2[mi][0], v0, v1);
            unpack2(acc2[mi][1], v2, v3);
            v0 += bsm[n0 + 0]; v1 += bsm[n0 + 1]; v2 += bsm[n0 + 2]; v3 += bsm[n0 + 3];
            if (act) { v0 = siluf(v0); v1 = siluf(v1); v2 = siluf(v2); v3 = siluf(v3); }
            *(float4*)&C[r * 128 + n0] = make_float4(v0, v1, v2, v3);
        }
    }
}

__global__ __launch_bounds__(256)
void gemm_kernel(const float* __restrict__ A, const float* __restrict__ W,
                 const float* __restrict__ bias, float* __restrict__ C, int M) {
    __shared__ float wsm[64 * PADW];
    __shared__ float asmv[64 * PADA];
    __shared__ float bsm[128];

    int tid = threadIdx.x;
    int row0 = blockIdx.x * 32;
    int nIdx = tid & 31, mIdx = tid >> 5;
    int n0 = nIdx * 4, m0 = mIdx * 4;
    if (tid < 128) bsm[tid] = bias[tid];

    unsigned long long acc2[4][2] = {};
    for (int kt = 0; kt < OUTD; kt += 64) {
        for (int idx = tid; idx < 128 * 64; idx += 256) {
            int o = idx >> 6, jj = idx & 63;
            wsm[jj * PADW + o] = W[o * OUTD + kt + jj];
        }
        for (int idx = tid; idx < 32 * 64; idx += 256) {
            int m = idx >> 6, jj = idx & 63;
            int r = row0 + m;
            asmv[jj * PADA + m] = (r < M) ? A[r * OUTD + kt + jj] : 0.0f;
        }
        __syncthreads();
        #pragma unroll 16
        for (int j = 0; j < 64; j++) {
            ulonglong2 wv = *(const ulonglong2*)&wsm[j * PADW + n0];
            float4 av = *(const float4*)&asmv[j * PADA + m0];
            unsigned long long a0 = pack2(av.x), a1 = pack2(av.y),
                               a2 = pack2(av.z), a3 = pack2(av.w);
            fma2(acc2[0][0], a0, wv.x); fma2(acc2[0][1], a0, wv.y);
            fma2(acc2[1][0], a1, wv.x); fma2(acc2[1][1], a1, wv.y);
            fma2(acc2[2][0], a2, wv.x); fma2(acc2[2][1], a2, wv.y);
            fma2(acc2[3][0], a3, wv.x); fma2(acc2[3][1], a3, wv.y);
        }
        __syncthreads();
    }
    #pragma unroll
    for (int mi = 0; mi < 4; mi++) {
        int r = row0 + m0 + mi;
        if (r < M) {
            float v0, v1, v2, v3;
            unpack2(acc2[mi][0], v0, v1);
            unpack2(acc2[mi][1], v2, v3);
            v0 += bsm[n0 + 0]; v1 += bsm[n0 + 1]; v2 += bsm[n0 + 2]; v3 += bsm[n0 + 3];
            *(float4*)&C[r * 128 + n0] = make_float4(v0, v1, v2, v3);
        }
    }
}

// ---------------- 4) sort: scan + scatter ----------------
__global__ __launch_bounds__(1024)
void scan_kernel(int Nn) {
    __shared__ int part[1024];
    int t = threadIdx.x;
    int chunk = (Nn + 1023) >> 10;
    int base = t * chunk;
    int local[16];
    int sum = 0;
    for (int i = 0; i < chunk; i++) {
        int idx = base + i;
        int c = (idx < Nn) ? g_cnt[idx] : 0;
        local[i] = sum; sum += c;
    }
    part[t] = sum;
    __syncthreads();
    for (int off = 1; off < 1024; off <<= 1) {
        int v = (t >= off) ? part[t - off] : 0;
        __syncthreads();
        part[t] += v;
        __syncthreads();
    }
    int pre = (t > 0) ? part[t - 1] : 0;
    for (int i = 0; i < chunk; i++) {
        int idx = base + i;
        if (idx < Nn) { int s0 = pre + local[i]; g_start[idx] = s0; g_off[idx] = s0; }
    }
    if (t == 0) g_start[Nn] = part[1023];
}

__global__ void scatter_kernel(int E) {
    int e = blockIdx.x * blockDim.x + threadIdx.x;
    if (e >= E) return;
    int nj = g_nj[e];
    int pos = atomicAdd(&g_off[nj], 1);
    g_elist[pos] = e;
}

// ---------------- 5) edge logits: cp.async w + register-pipelined t ----------------
#define ELB 128
#define KC 16
#define BUF_STRIDE 6208
#define OFF_TS 4096
#define OFF_BRE 12416
#define EL_SMEM ((12416 + 128) * 4)  // 50176 bytes

__global__ __launch_bounds__(256, 2)
void edge_logits_kernel(const float* __restrict__ T, const float* __restrict__ bre, int E) {
    extern __shared__ float sm[];
    uint32_t sb = smem_u32(sm);
    int tid = threadIdx.x;
    int warp = tid >> 5, lane = tid & 31;
    int eBase = blockIdx.x * ELB;
    if (tid < 128) sm[OFF_BRE + tid] = bre[tid];

    int d0 = lane * 4;
    unsigned long long acc[8][4] = {};

    // t register staging: thread covers edge eL, 8 floats starting at qq8
    int eL = tid >> 1, qq8 = (tid & 1) * 8;
    int myE = eBase + eL;
    bool eOK = (myE < E);
    const float* tRow = T + (long long)myE * EDIM + qq8;

    // w cp.async staging
    auto stage_w = [&](int buf, int kc) {
        uint32_t dwa = sb + (buf * BUF_STRIDE) * 4;
        uint32_t dwb = dwa + 2048 * 4;
        const float4* swa = g_wa + kc * KC * 32;
        const float4* swb = g_wb + kc * KC * 32;
        CP_ASYNC16(dwa + tid * 16, swa + tid);
        CP_ASYNC16(dwa + (tid + 256) * 16, swa + tid + 256);
        CP_ASYNC16(dwb + tid * 16, swb + tid);
        CP_ASYNC16(dwb + (tid + 256) * 16, swb + tid + 256);
        CP_COMMIT();
    };

    float treg[8];
    auto load_t = [&](int kc) {
        float4 a = eOK ? *(const float4*)(tRow + kc * KC)
                       : make_float4(0.f, 0.f, 0.f, 0.f);
        float4 b = eOK ? *(const float4*)(tRow + kc * KC + 4)
                       : make_float4(0.f, 0.f, 0.f, 0.f);
        treg[0] = a.x; treg[1] = a.y; treg[2] = a.z; treg[3] = a.w;
        treg[4] = b.x; treg[5] = b.y; treg[6] = b.z; treg[7] = b.w;
    };
    auto store_t = [&](int buf) {
        float* tb = sm + buf * BUF_STRIDE + OFF_TS;
        #pragma unroll
        for (int i = 0; i < 8; i++) tb[(qq8 + i) * 132 + eL] = treg[i];
    };

    // prologue
    stage_w(0, 0);
    load_t(0);

    for (int kc = 0; kc < EDIM / KC; kc++) {
        int buf = kc & 1;
        CP_WAIT0();             // w(kc) in smem
        store_t(buf);           // t(kc) regs -> smem (data long arrived)
        __syncthreads();

        if (kc + 1 < EDIM / KC) {
            load_t(kc + 1);     // fire LDGs; consumed next iteration
            stage_w(buf ^ 1, kc + 1);
        }

        const float* wa  = sm + buf * BUF_STRIDE;
        const float* wb  = sm + buf * BUF_STRIDE + 2048;
        const float* tsm = sm + buf * BUF_STRIDE + OFF_TS;
        #pragma unroll
        for (int j = 0; j < KC; j++) {
            ulonglong2 w01 = *(const ulonglong2*)&wa[j * 128 + d0];
            ulonglong2 w23 = *(const ulonglong2*)&wb[j * 128 + d0];
            const ulonglong2* tp = (const ulonglong2*)&tsm[j * 132 + warp * 16];
            ulonglong2 tA = tp[0], tB = tp[1], tC = tp[2], tD = tp[3];
            fma2(acc[0][0], tA.x, w01.x); fma2(acc[0][1], tA.x, w01.y); fma2(acc[0][2], tA.x, w23.x); fma2(acc[0][3], tA.x, w23.y);
            fma2(acc[1][0], tA.y, w01.x); fma2(acc[1][1], tA.y, w01.y); fma2(acc[1][2], tA.y, w23.x); fma2(acc[1][3], tA.y, w23.y);
            fma2(acc[2][0], tB.x, w01.x); fma2(acc[2][1], tB.x, w01.y); fma2(acc[2][2], tB.x, w23.x); fma2(acc[2][3], tB.x, w23.y);
            fma2(acc[3][0], tB.y, w01.x); fma2(acc[3][1], tB.y, w01.y); fma2(acc[3][2], tB.y, w23.x); fma2(acc[3][3], tB.y, w23.y);
            fma2(acc[4][0], tC.x, w01.x); fma2(acc[4][1], tC.x, w01.y); fma2(acc[4][2], tC.x, w23.x); fma2(acc[4][3], tC.x, w23.y);
            fma2(acc[5][0], tC.y, w01.x); fma2(acc[5][1], tC.y, w01.y); fma2(acc[5][2], tC.y, w23.x); fma2(acc[5][3], tC.y, w23.y);
            fma2(acc[6][0], tD.x, w01.x); fma2(acc[6][1], tD.x, w01.y); fma2(acc[6][2], tD.x, w23.x); fma2(acc[6][3], tD.x, w23.y);
            fma2(acc[7][0], tD.y, w01.x); fma2(acc[7][1], tD.y, w01.y); fma2(acc[7][2], tD.y, w23.x); fma2(acc[7][3], tD.y, w23.y);
        }
        __syncthreads();
    }

    int head = lane >> 2;
    const float* bsm = sm + OFF_BRE;
    float b0 = bsm[d0 + 0], b1 = bsm[d0 + 1], b2 = bsm[d0 + 2], b3 = bsm[d0 + 3];

    #pragma unroll
    for (int ei = 0; ei < 16; ei++) {
        int e = eBase + warp * 16 + ei;
        if (e >= E) continue;
        int nj = g_nj[e];
        int ni = g_ni[e];
        float4 q4 = *(const float4*)&g_q[ni * 128 + d0];
        float4 k4 = *(const float4*)&g_k[nj * 128 + d0];
        int p = ei >> 1;
        float lo0, hi0, lo1, hi1, lo2, hi2, lo3, hi3;
        unpack2(acc[p][0], lo0, hi0);
        unpack2(acc[p][1], lo1, hi1);
        unpack2(acc[p][2], lo2, hi2);
        unpack2(acc[p][3], lo3, hi3);
        float x0 = (ei & 1) ? hi0 : lo0;
        float x1 = (ei & 1) ? hi1 : lo1;
        float x2 = (ei & 1) ? hi2 : lo2;
        float x3 = (ei & 1) ? hi3 : lo3;
        x0 = silu_tanh(x0 + b0); x1 = silu_tanh(x1 + b1);
        x2 = silu_tanh(x2 + b2); x3 = silu_tanh(x3 + b3);
        float part = x0 * q4.x * k4.x + x1 * q4.y * k4.y
                   + x2 * q4.z * k4.z + x3 * q4.w * k4.w;
        part += __shfl_xor_sync(0xffffffffu, part, 1);
        part += __shfl_xor_sync(0xffffffffu, part, 2);
        if ((lane & 3) == 0) {
            float ex = __expf(fminf(part, 80.0f));
            g_a[e * 8 + head] = ex;
            atomicAdd(&g_s[ni * 8 + head], ex);
        }
    }
}

// ---------------- 6a) per-node P ----------------
__global__ __launch_bounds__(256)
void pmat_kernel(int Nn) {
    int tid = threadIdx.x;
    int h = tid >> 5;
    int o0 = (tid & 31) * 4;
    int n0 = blockIdx.x * 8;

    float acc[8][4];
    #pragma unroll
    for (int n = 0; n < 8; n++) { acc[n][0] = acc[n][1] = acc[n][2] = acc[n][3] = 0.0f; }

    #pragma unroll
    for (int dd = 0; dd < 16; dd++) {
        int d = h * 16 + dd;
        float4 w4 = *(const float4*)&g_WcT[d * OUTD + o0];
        #pragma unroll
        for (int n = 0; n < 8; n++) {
            int r = n0 + n;
            float vv = (r < Nn) ? g_v[r * OUTD + d] : 0.0f;
            acc[n][0] = fmaf(vv, w4.x, acc[n][0]);
            acc[n][1] = fmaf(vv, w4.y, acc[n][1]);
            acc[n][2] = fmaf(vv, w4.z, acc[n][2]);
            acc[n][3] = fmaf(vv, w4.w, acc[n][3]);
        }
    }
    #pragma unroll
    for (int n = 0; n < 8; n++) {
        int r = n0 + n;
        if (r < Nn) {
            *(float4*)&g_P[((r * 8 + h) * OUTD) + o0] =
                make_float4(acc[n][0], acc[n][1], acc[n][2], acc[n][3]);
        }
    }
}

// ---------------- 6b) invert sums ----------------
__global__ void sinv_kernel(int NH) {
    int i = blockIdx.x * blockDim.x + threadIdx.x;
    if (i < NH) g_s[i] = 0.25f / (g_s[i] + 1e-16f);
}

// ---------------- 7) output ----------------
__global__ __launch_bounds__(256)
void out_kernel(const float* __restrict__ bc, float* __restrict__ outp, int E) {
    int n = blockIdx.x;
    int start = g_start[n], end = g_start[n + 1];
    if (start == end) return;
    int warp = threadIdx.x >> 5, lane = threadIdx.x & 31;
    int o0 = lane * 4;

    ulonglong2 P2[8];
    #pragma unroll
    for (int h = 0; h < 8; h++)
        P2[h] = *(const ulonglong2*)&g_P[((n * 8 + h) * OUTD) + o0];
    ulonglong2 bc2 = *(const ulonglong2*)&bc[o0];

    for (int i = start + warp; i < end; i += 8) {
        int e = g_elist[i];
        float w = 0.0f;
        if (lane < 8) {
            int ni = g_ni[e];
            w = g_a[e * 8 + lane] * g_s[ni * 8 + lane];
        }
        unsigned long long a0 = bc2.x, a1 = bc2.y;
        #pragma unroll
        for (int h = 0; h < 8; h++) {
            unsigned long long wh = pack2(__shfl_sync(0xffffffffu, w, h));
            fma2(a0, wh, P2[h].x);
            fma2(a1, wh, P2[h].y);
        }
        ulonglong2 res; res.x = a0; res.y = a1;
        *(ulonglong2*)&outp[(long long)e * 128 + o0] = res;
    }
}

// ---------------- host launcher ----------------
extern "C" void kernel_launch(void* const* d_in, const int* in_sizes, int n_in,
                              void* d_out, int out_size) {
    const float* h    = (const float*)d_in[0];
    const float* tij  = (const float*)d_in[1];
    const void*  eidx = d_in[2];
    const float* Wq   = (const float*)d_in[3];
    const float* bq   = (const float*)d_in[4];
    const float* Wk   = (const float*)d_in[5];
    const float* bk   = (const float*)d_in[6];
    const float* W1   = (const float*)d_in[7];
    const float* b1   = (const float*)d_in[8];
    const float* W2   = (const float*)d_in[9];
    const float* b2   = (const float*)d_in[10];
    const float* Wre  = (const float*)d_in[11];
    const float* bre  = (const float*)d_in[12];
    const float* Wc   = (const float*)d_in[13];
    const float* bc   = (const float*)d_in[14];

    int Nn = in_sizes[0] / DDIM;     // 10000
    int E  = in_sizes[1] / EDIM;     // 640000

    float *pq, *pk, *pu, *pv;
    cudaGetSymbolAddress((void**)&pq, g_q);
    cudaGetSymbolAddress((void**)&pk, g_k);
    cudaGetSymbolAddress((void**)&pu, g_u);
    cudaGetSymbolAddress((void**)&pv, g_v);

    static cudaStream_t s1 = nullptr, s2 = nullptr;
    static cudaEvent_t evFork = nullptr, evQK = nullptr, evB = nullptr,
                       evConv = nullptr, evScat = nullptr;
    if (!s1) {
        cudaFuncSetAttribute(edge_logits_kernel, cudaFuncAttributeMaxDynamicSharedMemorySize, EL_SMEM);
        cudaStreamCreateWithFlags(&s1, cudaStreamNonBlocking);
        cudaStreamCreateWithFlags(&s2, cudaStreamNonBlocking);
        cudaEventCreateWithFlags(&evFork, cudaEventDisableTiming);
        cudaEventCreateWithFlags(&evQK,   cudaEventDisableTiming);
        cudaEventCreateWithFlags(&evB,    cudaEventDisableTiming);
        cudaEventCreateWithFlags(&evConv, cudaEventDisableTiming);
        cudaEventCreateWithFlags(&evScat, cudaEventDisableTiming);
    }

    // launch #1: init (+ index-width detect)
    {
        int total = Nn * HDS;
        if (total < OUTD * OUTD) total = OUTD * OUTD;
        if (total < Nn) total = Nn;
        init_kernel<<<(total + 255) / 256, 256>>>(Wc, (const unsigned*)eidx, Nn * HDS, Nn);
    }

    cudaEventRecord(evFork, 0);
    cudaStreamWaitEvent(s1, evFork, 0);

    // launch #2: gemm3 (q,k,u) on s1
    int gb = (Nn + 31) / 32;
    {
        dim3 grid(gb, 3);
        gemm3_kernel<<<grid, 256, 0, s1>>>(h, Wq, bq, Wk, bk, W1, b1, pq, pk, pu, Nn);
    }
    cudaEventRecord(evQK, s1);

    // launch #3: convert + hist + wdup planes on stream 0
    {
        int eBlocks = (E + 255) / 256;
        convert_hist_wdup_kernel<<<eBlocks + 16, 256>>>(eidx, Wre, E, eBlocks);
    }
    cudaEventRecord(evConv, 0);

    // launch #4: edge_logits (ncu slot)
    cudaStreamWaitEvent(0, evQK, 0);
    edge_logits_kernel<<<(E + ELB - 1) / ELB, 256, EL_SMEM>>>(tij, bre, E);

    // side branches
    gemm_kernel<<<gb, 256, 0, s1>>>(pu, W2, b2, pv, Nn);
    pmat_kernel<<<(Nn + 7) / 8, 256, 0, s1>>>(Nn);
    cudaEventRecord(evB, s1);

    cudaStreamWaitEvent(s2, evConv, 0);
    scan_kernel<<<1, 1024, 0, s2>>>(Nn);
    scatter_kernel<<<(E + 255) / 256, 256, 0, s2>>>(E);
    cudaEventRecord(evScat, s2);

    // critical path
    sinv_kernel<<<(Nn * HDS + 255) / 256, 256>>>(Nn * HDS);

    cudaStreamWaitEvent(0, evB, 0);
    cudaStreamWaitEvent(0, evScat, 0);
    out_kernel<<<Nn, 256>>>(bc, (float*)d_out, E);
}

// round 16
// speedup vs baseline: 1.0562x; 1.0016x over previous
#include <cuda_runtime.h>
#include <cstdint>

// ---------------- problem constants ----------------
#define NMAX 10000
#define EMAX 640000
#define DDIM 128
#define EDIM 64
#define HDS  8
#define OUTD 128

// ---------------- device scratch ----------------
__device__ __align__(16) float g_q[NMAX * DDIM];
__device__ __align__(16) float g_k[NMAX * DDIM];
__device__ __align__(16) float g_u[NMAX * OUTD];
__device__ __align__(16) float g_v[NMAX * OUTD];
__device__ __align__(16) float g_P[NMAX * HDS * OUTD];
__device__ __align__(16) float g_a[EMAX * HDS];
__device__ __align__(16) float g_s[NMAX * HDS];
__device__ __align__(16) float g_WcT[OUTD * OUTD];
// duplicated Wre, two conflict-free planes (float4 per lane)
__device__ __align__(16) float4 g_wa[EDIM * 32];
__device__ __align__(16) float4 g_wb[EDIM * 32];
__device__ int g_is64;
__device__ int g_nj[EMAX];
__device__ int g_ni[EMAX];
__device__ int g_cnt[NMAX];
__device__ int g_start[NMAX + 1];
__device__ int g_off[NMAX];
__device__ int g_elist[EMAX];

// ---------------- helpers ----------------
__device__ __forceinline__ unsigned long long pack2(float x) {
    unsigned long long r; unsigned u = __float_as_uint(x);
    asm("mov.b64 %0, {%1, %1};" : "=l"(r) : "r"(u));
    return r;
}
__device__ __forceinline__ void fma2(unsigned long long& d, unsigned long long a, unsigned long long b) {
    asm("fma.rn.f32x2 %0, %1, %2, %0;" : "+l"(d) : "l"(a), "l"(b));
}
__device__ __forceinline__ void unpack2(unsigned long long v, float& x, float& y) {
    unsigned a, b;
    asm("mov.b64 {%0, %1}, %2;" : "=r"(a), "=r"(b) : "l"(v));
    x = __uint_as_float(a); y = __uint_as_float(b);
}
__device__ __forceinline__ float siluf(float x) { return __fdividef(x, 1.0f + __expf(-x)); }
__device__ __forceinline__ float silu_tanh(float x) {
    float t;
    float hx = 0.5f * x;
    asm("tanh.approx.f32 %0, %1;" : "=f"(t) : "f"(hx));
    return fmaf(hx, t, hx);
}
__device__ __forceinline__ int load_idx(const void* eidx, int is64, long long pos) {
    return is64 ? (int)((const long long*)eidx)[pos] : ((const int*)eidx)[pos];
}
__device__ __forceinline__ uint32_t smem_u32(const void* p) {
    uint32_t a;
    asm("{ .reg .u64 t; cvta.to.shared.u64 t, %1; cvt.u32.u64 %0, t; }" : "=r"(a) : "l"(p));
    return a;
}
#define CP_ASYNC16(dst_u32, src_ptr) \
    asm volatile("cp.async.ca.shared.global [%0], [%1], 16;" :: "r"(dst_u32), "l"(src_ptr))
#define CP_COMMIT() asm volatile("cp.async.commit_group;" ::: "memory")
#define CP_WAIT0()  asm volatile("cp.async.wait_group 0;" ::: "memory")

// ---------------- 1) init (+ index-width detection in block 0) ----------------
__global__ void init_kernel(const float* __restrict__ Wc, const unsigned* __restrict__ ew,
                            int NH, int Nn) {
    if (blockIdx.x == 0) {
        __shared__ int any;
        if (threadIdx.x == 0) any = 0;
        __syncthreads();
        #pragma unroll
        for (int k = 0; k < 4; k++) {
            int i = threadIdx.x + k * 256;
            if (ew[i * 2 + 1] != 0u) any = 1;
        }
        __syncthreads();
        if (threadIdx.x == 0) g_is64 = (any == 0) ? 1 : 0;
    }
    int i = blockIdx.x * blockDim.x + threadIdx.x;
    if (i < NH) g_s[i] = 0.0f;
    if (i < Nn) g_cnt[i] = 0;
    if (i < OUTD * OUTD) {
        int o = i >> 7, d = i & 127;
        g_WcT[d * OUTD + o] = Wc[i];
    }
}

// ---------------- 2) convert indices + histogram, fused with Wre plane prep ----------------
__global__ void convert_hist_wdup_kernel(const void* __restrict__ eidx,
                                         const float* __restrict__ Wre,
                                         int E, int eBlocks) {
    if (blockIdx.x >= eBlocks) {
        int idx = (blockIdx.x - eBlocks) * blockDim.x + threadIdx.x;
        if (idx < EDIM * 32 * 2) {
            int which = idx >> 11;
            int rem = idx & 2047;
            int j = rem >> 5, l = rem & 31;
            int d0 = l * 4 + which * 2;
            float v0 = Wre[d0 * EDIM + j];
            float v1 = Wre[(d0 + 1) * EDIM + j];
            float4 out = make_float4(v0, v0, v1, v1);
            if (which == 0) g_wa[j * 32 + l] = out;
            else            g_wb[j * 32 + l] = out;
        }
        return;
    }
    int e = blockIdx.x * blockDim.x + threadIdx.x;
    if (e >= E) return;
    int is64 = g_is64;
    int nj = load_idx(eidx, is64, e);
    int ni = load_idx(eidx, is64, (long long)E + e);
    g_nj[e] = nj;
    g_ni[e] = ni;
    atomicAdd(&g_cnt[nj], 1);
}

// ---------------- 3) node GEMMs (32-row tile, 4x4 reg block) ----------------
#define PADW 132
#define PADA 36
__global__ __launch_bounds__(256)
void gemm3_kernel(const float* __restrict__ A,
                  const float* __restrict__ W0, const float* __restrict__ B0,
                  const float* __restrict__ W1p, const float* __restrict__ B1,
                  const float* __restrict__ W2p, const float* __restrict__ B2,
                  float* __restrict__ C0, float* __restrict__ C1, float* __restrict__ C2,
                  int M) {
    const float* W = (blockIdx.y == 0) ? W0 : (blockIdx.y == 1) ? W1p : W2p;
    const float* bias = (blockIdx.y == 0) ? B0 : (blockIdx.y == 1) ? B1 : B2;
    float* C = (blockIdx.y == 0) ? C0 : (blockIdx.y == 1) ? C1 : C2;
    int act = (blockIdx.y == 2);

    __shared__ float wsm[64 * PADW];
    __shared__ float asmv[64 * PADA];
    __shared__ float bsm[128];

    int tid = threadIdx.x;
    int row0 = blockIdx.x * 32;
    int nIdx = tid & 31, mIdx = tid >> 5;
    int n0 = nIdx * 4, m0 = mIdx * 4;
    if (tid < 128) bsm[tid] = bias[tid];

    unsigned long long acc2[4][2] = {};
    for (int kt = 0; kt < DDIM; kt += 64) {
        for (int idx = tid; idx < 128 * 64; idx += 256) {
            int o = idx >> 6, jj = idx & 63;
            wsm[jj * PADW + o] = W[o * DDIM + kt + jj];
        }
        for (int idx = tid; idx < 32 * 64; idx += 256) {
            int m = idx >> 6, jj = idx & 63;
            int r = row0 + m;
            asmv[jj * PADA + m] = (r < M) ? A[r * DDIM + kt + jj] : 0.0f;
        }
        __syncthreads();
        #pragma unroll 16
        for (int j = 0; j < 64; j++) {
            ulonglong2 wv = *(const ulonglong2*)&wsm[j * PADW + n0];
            float4 av = *(const float4*)&asmv[j * PADA + m0];
            unsigned long long a0 = pack2(av.x), a1 = pack2(av.y),
                               a2 = pack2(av.z), a3 = pack2(av.w);
            fma2(acc2[0][0], a0, wv.x); fma2(acc2[0][1], a0, wv.y);
            fma2(acc2[1][0], a1, wv.x); fma2(acc2[1][1], a1, wv.y);
            fma2(acc2[2][0], a2, wv.x); fma2(acc2[2][1], a2, wv.y);
            fma2(acc2[3][0], a3, wv.x); fma2(acc2[3][1], a3, wv.y);
        }
        __syncthreads();
    }
    #pragma unroll
    for (int mi = 0; mi < 4; mi++) {
        int r = row0 + m0 + mi;
        if (r < M) {
            float v0, v1, v2, v3;
            unpack2(acc2[mi][0], v0, v1);
            unpack2(acc2[mi][1], v2, v3);
            v0 += bsm[n0 + 0]; v1 += bsm[n0 + 1]; v2 += bsm[n0 + 2]; v3 += bsm[n0 + 3];
            if (act) { v0 = siluf(v0); v1 = siluf(v1); v2 = siluf(v2); v3 = siluf(v3); }
            *(float4*)&C[r * 128 + n0] = make_float4(v0, v1, v2, v3);
        }
    }
}

__global__ __launch_bounds__(256)
void gemm_kernel(const float* __restrict__ A, const float* __restrict__ W,
                 const float* __restrict__ bias, float* __restrict__ C, int M) {
    __shared__ float wsm[64 * PADW];
    __shared__ float asmv[64 * PADA];
    __shared__ float bsm[128];

    int tid = threadIdx.x;
    int row0 = blockIdx.x * 32;
    int nIdx = tid & 31, mIdx = tid >> 5;
    int n0 = nIdx * 4, m0 = mIdx * 4;
    if (tid < 128) bsm[tid] = bias[tid];

    unsigned long long acc2[4][2] = {};
    for (int kt = 0; kt < OUTD; kt += 64) {
        for (int idx = tid; idx < 128 * 64; idx += 256) {
            int o = idx >> 6, jj = idx & 63;
            wsm[jj * PADW + o] = W[o * OUTD + kt + jj];
        }
        for (int idx = tid; idx < 32 * 64; idx += 256) {
            int m = idx >> 6, jj = idx & 63;
            int r = row0 + m;
            asmv[jj * PADA + m] = (r < M) ? A[r * OUTD + kt + jj] : 0.0f;
        }
        __syncthreads();
        #pragma unroll 16
        for (int j = 0; j < 64; j++) {
            ulonglong2 wv = *(const ulonglong2*)&wsm[j * PADW + n0];
            float4 av = *(const float4*)&asmv[j * PADA + m0];
            unsigned long long a0 = pack2(av.x), a1 = pack2(av.y),
                               a2 = pack2(av.z), a3 = pack2(av.w);
            fma2(acc2[0][0], a0, wv.x); fma2(acc2[0][1], a0, wv.y);
            fma2(acc2[1][0], a1, wv.x); fma2(acc2[1][1], a1, wv.y);
            fma2(acc2[2][0], a2, wv.x); fma2(acc2[2][1], a2, wv.y);
            fma2(acc2[3][0], a3, wv.x); fma2(acc2[3][1], a3, wv.y);
        }
        __syncthreads();
    }
    #pragma unroll
    for (int mi = 0; mi < 4; mi++) {
        int r = row0 + m0 + mi;
        if (r < M) {
            float v0, v1, v2, v3;
            unpack2(acc2[mi][0], v0, v1);
            unpack2(acc2[mi][1], v2, v3);
            v0 += bsm[n0 + 0]; v1 += bsm[n0 + 1]; v2 += bsm[n0 + 2]; v3 += bsm[n0 + 3];
            *(float4*)&C[r * 128 + n0] = make_float4(v0, v1, v2, v3);
        }
    }
}

// ---------------- 4) sort: scan + scatter ----------------
__global__ __launch_bounds__(1024)
void scan_kernel(int Nn) {
    __shared__ int part[1024];
    int t = threadIdx.x;
    int chunk = (Nn + 1023) >> 10;
    int base = t * chunk;
    int local[16];
    int sum = 0;
    for (int i = 0; i < chunk; i++) {
        int idx = base + i;
        int c = (idx < Nn) ? g_cnt[idx] : 0;
        local[i] = sum; sum += c;
    }
    part[t] = sum;
    __syncthreads();
    for (int off = 1; off < 1024; off <<= 1) {
        int v = (t >= off) ? part[t - off] : 0;
        __syncthreads();
        part[t] += v;
        __syncthreads();
    }
    int pre = (t > 0) ? part[t - 1] : 0;
    for (int i = 0; i < chunk; i++) {
        int idx = base + i;
        if (idx < Nn) { int s0 = pre + local[i]; g_start[idx] = s0; g_off[idx] = s0; }
    }
    if (t == 0) g_start[Nn] = part[1023];
}

__global__ void scatter_kernel(int E) {
    int e = blockIdx.x * blockDim.x + threadIdx.x;
    if (e >= E) return;
    int nj = g_nj[e];
    int pos = atomicAdd(&g_off[nj], 1);
    g_elist[pos] = e;
}

// ---------------- 5) edge logits: PERSISTENT, w resident in smem ----------------
#define ELB 128
#define KC 16
#define NBLK 296
// smem floats: wall[4][4096] = 16384; tbuf[2][16*132=2112] = 4224; bre 128
#define OFF_T 16384
#define T_STRIDE 2112
#define OFF_BRE (16384 + 4224)
#define EL_SMEM ((16384 + 4224 + 128) * 4)   // 82944 bytes

__global__ __launch_bounds__(256, 2)
void edge_logits_kernel(const float* __restrict__ T, const float* __restrict__ bre, int E) {
    extern __shared__ float sm[];
    uint32_t sb = smem_u32(sm);
    int tid = threadIdx.x;
    int warp = tid >> 5, lane = tid & 31;
    if (tid < 128) sm[OFF_BRE + tid] = bre[tid];

    // load ALL w planes once: 4096 float4 via cp.async (16 per thread)
    {
        #pragma unroll
        for (int i = 0; i < 16; i++) {
            int idx = tid + i * 256;          // 0..4095 float4
            int kc = idx >> 10, r = idx & 1023;
            int plane = r >> 9, x = r & 511;
            const float4* src = (plane ? g_wb : g_wa) + kc * 512 + x;
            CP_ASYNC16(sb + (uint32_t)idx * 16, src);
        }
        CP_COMMIT();
    }

    int d0 = lane * 4;
    int eL = tid >> 1, qq8 = (tid & 1) * 8;   // t staging role
    int nTiles = (E + ELB - 1) / ELB;

    float treg[8];
    auto load_t = [&](int tile, int kc) {
        long long e = (long long)tile * ELB + eL;
        bool ok = (tile < nTiles) && (e < E);
        const float* tRow = T + e * EDIM + qq8 + kc * KC;
        float4 a = ok ? *(const float4*)tRow       : make_float4(0.f, 0.f, 0.f, 0.f);
        float4 b = ok ? *(const float4*)(tRow + 4) : make_float4(0.f, 0.f, 0.f, 0.f);
        treg[0] = a.x; treg[1] = a.y; treg[2] = a.z; treg[3] = a.w;
        treg[4] = b.x; treg[5] = b.y; treg[6] = b.z; treg[7] = b.w;
    };
    auto store_t = [&](int buf) {
        float* tb = sm + OFF_T + buf * T_STRIDE;
        #pragma unroll
        for (int i = 0; i < 8; i++) tb[(qq8 + i) * 132 + eL] = treg[i];
    };

    // prologue: first tile's first chunk into regs; wait for w
    int tile0 = blockIdx.x;
    load_t(tile0, 0);
    CP_WAIT0();
    __syncthreads();

    for (int tile = tile0; tile < nTiles; tile += NBLK) {
        int eBase = tile * ELB;
        unsigned long long acc[8][4] = {};

        #pragma unroll
        for (int kc = 0; kc < EDIM / KC; kc++) {
            int buf = kc & 1;
            store_t(buf);
            __syncthreads();
            if (kc + 1 < EDIM / KC) load_t(tile, kc + 1);
            else                    load_t(tile + NBLK, 0);

            const float* wa  = sm + kc * 4096;          // resident
            const float* wb  = sm + kc * 4096 + 2048;
            const float* tsm = sm + OFF_T + buf * T_STRIDE;
            #pragma unroll
            for (int j = 0; j < KC; j++) {
                ulonglong2 w01 = *(const ulonglong2*)&wa[j * 128 + d0];
                ulonglong2 w23 = *(const ulonglong2*)&wb[j * 128 + d0];
                const ulonglong2* tp = (const ulonglong2*)&tsm[j * 132 + warp * 16];
                ulonglong2 tA = tp[0], tB = tp[1], tC = tp[2], tD = tp[3];
                fma2(acc[0][0], tA.x, w01.x); fma2(acc[0][1], tA.x, w01.y); fma2(acc[0][2], tA.x, w23.x); fma2(acc[0][3], tA.x, w23.y);
                fma2(acc[1][0], tA.y, w01.x); fma2(acc[1][1], tA.y, w01.y); fma2(acc[1][2], tA.y, w23.x); fma2(acc[1][3], tA.y, w23.y);
                fma2(acc[2][0], tB.x, w01.x); fma2(acc[2][1], tB.x, w01.y); fma2(acc[2][2], tB.x, w23.x); fma2(acc[2][3], tB.x, w23.y);
                fma2(acc[3][0], tB.y, w01.x); fma2(acc[3][1], tB.y, w01.y); fma2(acc[3][2], tB.y, w23.x); fma2(acc[3][3], tB.y, w23.y);
                fma2(acc[4][0], tC.x, w01.x); fma2(acc[4][1], tC.x, w01.y); fma2(acc[4][2], tC.x, w23.x); fma2(acc[4][3], tC.x, w23.y);
                fma2(acc[5][0], tC.y, w01.x); fma2(acc[5][1], tC.y, w01.y); fma2(acc[5][2], tC.y, w23.x); fma2(acc[5][3], tC.y, w23.y);
                fma2(acc[6][0], tD.x, w01.x); fma2(acc[6][1], tD.x, w01.y); fma2(acc[6][2], tD.x, w23.x); fma2(acc[6][3], tD.x, w23.y);
                fma2(acc[7][0], tD.y, w01.x); fma2(acc[7][1], tD.y, w01.y); fma2(acc[7][2], tD.y, w23.x); fma2(acc[7][3], tD.y, w23.y);
            }
            __syncthreads();
        }

        // epilogue for this tile
        int head = lane >> 2;
        const float* bsm = sm + OFF_BRE;
        float b0 = bsm[d0 + 0], b1 = bsm[d0 + 1], b2 = bsm[d0 + 2], b3 = bsm[d0 + 3];

        #pragma unroll
        for (int ei = 0; ei < 16; ei++) {
            int e = eBase + warp * 16 + ei;
            if (e >= E) continue;
            int nj = g_nj[e];
            int ni = g_ni[e];
            float4 q4 = *(const float4*)&g_q[ni * 128 + d0];
            float4 k4 = *(const float4*)&g_k[nj * 128 + d0];
            int p = ei >> 1;
            float lo0, hi0, lo1, hi1, lo2, hi2, lo3, hi3;
            unpack2(acc[p][0], lo0, hi0);
            unpack2(acc[p][1], lo1, hi1);
            unpack2(acc[p][2], lo2, hi2);
            unpack2(acc[p][3], lo3, hi3);
            float x0 = (ei & 1) ? hi0 : lo0;
            float x1 = (ei & 1) ? hi1 : lo1;
            float x2 = (ei & 1) ? hi2 : lo2;
            float x3 = (ei & 1) ? hi3 : lo3;
            x0 = silu_tanh(x0 + b0); x1 = silu_tanh(x1 + b1);
            x2 = silu_tanh(x2 + b2); x3 = silu_tanh(x3 + b3);
            float part = x0 * q4.x * k4.x + x1 * q4.y * k4.y
                       + x2 * q4.z * k4.z + x3 * q4.w * k4.w;
            part += __shfl_xor_sync(0xffffffffu, part, 1);
            part += __shfl_xor_sync(0xffffffffu, part, 2);
            if ((lane & 3) == 0) {
                float ex = __expf(fminf(part, 80.0f));
                g_a[e * 8 + head] = ex;
                atomicAdd(&g_s[ni * 8 + head], ex);
            }
        }
    }
}

// ---------------- 6a) per-node P ----------------
__global__ __launch_bounds__(256)
void pmat_kernel(int Nn) {
    int tid = threadIdx.x;
    int h = tid >> 5;
    int o0 = (tid & 31) * 4;
    int n0 = blockIdx.x * 8;

    float acc[8][4];
    #pragma unroll
    for (int n = 0; n < 8; n++) { acc[n][0] = acc[n][1] = acc[n][2] = acc[n][3] = 0.0f; }

    #pragma unroll
    for (int dd = 0; dd < 16; dd++) {
        int d = h * 16 + dd;
        float4 w4 = *(const float4*)&g_WcT[d * OUTD + o0];
        #pragma unroll
        for (int n = 0; n < 8; n++) {
            int r = n0 + n;
            float vv = (r < Nn) ? g_v[r * OUTD + d] : 0.0f;
            acc[n][0] = fmaf(vv, w4.x, acc[n][0]);
            acc[n][1] = fmaf(vv, w4.y, acc[n][1]);
            acc[n][2] = fmaf(vv, w4.z, acc[n][2]);
            acc[n][3] = fmaf(vv, w4.w, acc[n][3]);
        }
    }
    #pragma unroll
    for (int n = 0; n < 8; n++) {
        int r = n0 + n;
        if (r < Nn) {
            *(float4*)&g_P[((r * 8 + h) * OUTD) + o0] =
                make_float4(acc[n][0], acc[n][1], acc[n][2], acc[n][3]);
        }
    }
}

// ---------------- 6b) invert sums ----------------
__global__ void sinv_kernel(int NH) {
    int i = blockIdx.x * blockDim.x + threadIdx.x;
    if (i < NH) g_s[i] = 0.25f / (g_s[i] + 1e-16f);
}

// ---------------- 7) output ----------------
__global__ __launch_bounds__(256)
void out_kernel(const float* __restrict__ bc, float* __restrict__ outp, int E) {
    int n = blockIdx.x;
    int start = g_start[n], end = g_start[n + 1];
    if (start == end) return;
    int warp = threadIdx.x >> 5, lane = threadIdx.x & 31;
    int o0 = lane * 4;

    ulonglong2 P2[8];
    #pragma unroll
    for (int h = 0; h < 8; h++)
        P2[h] = *(const ulonglong2*)&g_P[((n * 8 + h) * OUTD) + o0];
    ulonglong2 bc2 = *(const ulonglong2*)&bc[o0];

    for (int i = start + warp; i < end; i += 8) {
        int e = g_elist[i];
        float w = 0.0f;
        if (lane < 8) {
            int ni = g_ni[e];
            w = g_a[e * 8 + lane] * g_s[ni * 8 + lane];
        }
        unsigned long long a0 = bc2.x, a1 = bc2.y;
        #pragma unroll
        for (int h = 0; h < 8; h++) {
            unsigned long long wh = pack2(__shfl_sync(0xffffffffu, w, h));
            fma2(a0, wh, P2[h].x);
            fma2(a1, wh, P2[h].y);
        }
        ulonglong2 res; res.x = a0; res.y = a1;
        *(ulonglong2*)&outp[(long long)e * 128 + o0] = res;
    }
}

// ---------------- host launcher ----------------
extern "C" void kernel_launch(void* const* d_in, const int* in_sizes, int n_in,
                              void* d_out, int out_size) {
    const float* h    = (const float*)d_in[0];
    const float* tij  = (const float*)d_in[1];
    const void*  eidx = d_in[2];
    const float* Wq   = (const float*)d_in[3];
    const float* bq   = (const float*)d_in[4];
    const float* Wk   = (const float*)d_in[5];
    const float* bk   = (const float*)d_in[6];
    const float* W1   = (const float*)d_in[7];
    const float* b1   = (const float*)d_in[8];
    const float* W2   = (const float*)d_in[9];
    const float* b2   = (const float*)d_in[10];
    const float* Wre  = (const float*)d_in[11];
    const float* bre  = (const float*)d_in[12];
    const float* Wc   = (const float*)d_in[13];
    const float* bc   = (const float*)d_in[14];

    int Nn = in_sizes[0] / DDIM;     // 10000
    int E  = in_sizes[1] / EDIM;     // 640000

    float *pq, *pk, *pu, *pv;
    cudaGetSymbolAddress((void**)&pq, g_q);
    cudaGetSymbolAddress((void**)&pk, g_k);
    cudaGetSymbolAddress((void**)&pu, g_u);
    cudaGetSymbolAddress((void**)&pv, g_v);

    static cudaStream_t s1 = nullptr, s2 = nullptr;
    static cudaEvent_t evFork = nullptr, evQK = nullptr, evB = nullptr,
                       evConv = nullptr, evScat = nullptr;
    if (!s1) {
        cudaFuncSetAttribute(edge_logits_kernel, cudaFuncAttributeMaxDynamicSharedMemorySize, EL_SMEM);
        cudaStreamCreateWithFlags(&s1, cudaStreamNonBlocking);
        cudaStreamCreateWithFlags(&s2, cudaStreamNonBlocking);
        cudaEventCreateWithFlags(&evFork, cudaEventDisableTiming);
        cudaEventCreateWithFlags(&evQK,   cudaEventDisableTiming);
        cudaEventCreateWithFlags(&evB,    cudaEventDisableTiming);
        cudaEventCreateWithFlags(&evConv, cudaEventDisableTiming);
        cudaEventCreateWithFlags(&evScat, cudaEventDisableTiming);
    }

    // launch #1: init (+ index-width detect)
    {
        int total = Nn * HDS;
        if (total < OUTD * OUTD) total = OUTD * OUTD;
        if (total < Nn) total = Nn;
        init_kernel<<<(total + 255) / 256, 256>>>(Wc, (const unsigned*)eidx, Nn * HDS, Nn);
    }

    cudaEventRecord(evFork, 0);
    cudaStreamWaitEvent(s1, evFork, 0);

    // launch #2: gemm3 (q,k,u) on s1
    int gb = (Nn + 31) / 32;
    {
        dim3 grid(gb, 3);
        gemm3_kernel<<<grid, 256, 0, s1>>>(h, Wq, bq, Wk, bk, W1, b1, pq, pk, pu, Nn);
    }
    cudaEventRecord(evQK, s1);

    // launch #3: convert + hist + wdup planes on stream 0
    {
        int eBlocks = (E + 255) / 256;
        convert_hist_wdup_kernel<<<eBlocks + 16, 256>>>(eidx, Wre, E, eBlocks);
    }
    cudaEventRecord(evConv, 0);

    // launch #4: edge_logits (persistent; ncu slot)
    cudaStreamWaitEvent(0, evQK, 0);
    edge_logits_kernel<<<NBLK, 256, EL_SMEM>>>(tij, bre, E);

    // side branches
    gemm_kernel<<<gb, 256, 0, s1>>>(pu, W2, b2, pv, Nn);
    pmat_kernel<<<(Nn + 7) / 8, 256, 0, s1>>>(Nn);
    cudaEventRecord(evB, s1);

    cudaStreamWaitEvent(s2, evConv, 0);
    scan_kernel<<<1, 1024, 0, s2>>>(Nn);
    scatter_kernel<<<(E + 255) / 256, 256, 0, s2>>>(E);
    cudaEventRecord(evScat, s2);

    // critical path
    sinv_kernel<<<(Nn * HDS + 255) / 256, 256>>>(Nn * HDS);

    cudaStreamWaitEvent(0, evB, 0);
    cudaStreamWaitEvent(0, evScat, 0);
    out_kernel<<<Nn, 256>>>(bc, (float*)d_out, E);
}